// round 8
// baseline (speedup 1.0000x reference)
#include <cuda_runtime.h>
#include <cstddef>
#include <cstdint>

// Problem constants
#define BB   2048
#define TT   512
#define D_IN 4
#define HH   64
#define LL   4
#define OUTN 5
#define G4   256   // 4*H

#define PLANE ((size_t)TT * BB * HH)   // floats per gate plane

// -------------------------- device scratch --------------------------------
__device__ float g_hsA[(size_t)TT * BB * HH];     // 256 MB ping
__device__ float g_hsB[(size_t)TT * BB * HH];     // 256 MB pong
__device__ float g_xg[4 * PLANE];                 // 1 GB: 4 gate planes [trow][u]
__device__ float g_W0sc[G4 * 68];                 // layer0 combined [gate][68]
__device__ float g_Whhsc[LL][G4 * HH];            // W_hh scalar [gate][64]
__device__ float g_bias[LL][G4];

__device__ __forceinline__ float sigf(float x) {
    return __fdividef(1.0f, 1.0f + __expf(-x));
}
__device__ __forceinline__ float tanhg(float x) {
    return __fdividef(2.0f, 1.0f + __expf(-2.0f * x)) - 1.0f;
}
__device__ __forceinline__ float tf32_rna(float x) {
    float r;
    asm("cvt.rna.tf32.f32 %0, %1;" : "=f"(r) : "f"(x));
    return r;
}

// ---------------------------------------------------------------------------
// Weight prep (layer0 combined, W_hh scalar, fused bias).
// ---------------------------------------------------------------------------
__global__ void prep_kernel(const float* __restrict__ W_ih0,
                            const float* __restrict__ W_hh,
                            const float* __restrict__ b_ih,
                            const float* __restrict__ b_hh) {
    int idx = blockIdx.x * blockDim.x + threadIdx.x;   // l*256*128 + gate*128 + k
    if (idx >= LL * G4 * 128) return;
    int k    = idx & 127;
    int gate = (idx >> 7) & 255;
    int l    = idx >> 15;

    if (k == 0)
        g_bias[l][gate] = b_ih[l * G4 + gate] + b_hh[l * G4 + gate];

    if (l == 0) {
        if (k < D_IN)           g_W0sc[gate * 68 + k] = W_ih0[gate * D_IN + k];
        else if (k < D_IN + HH) g_W0sc[gate * 68 + k] = W_hh[gate * HH + (k - D_IN)];
    } else {
        if (k >= HH) {
            int kk = k - HH;
            g_Whhsc[l][gate * HH + kk] = W_hh[((size_t)l * G4 + gate) * HH + kk];
        }
    }
}

// ====================== mma.sync tf32 xg GEMM ==============================
// xg planes: plane q holds preact of gate block q (+bias) for all rows/units.
//   D[1M,256] = hs[1M,64] x W^T[64,256], 2-pass tf32 (HH + LH).
//   CTA 256 thr = 8 warps: wm = wid&1 (64-row half), wn = wid>>1 (64-col
//   quarter = gate block). Warp tile: 64x64 via m16n8k8 frags.

#define XG_GRID   1024
#define XG_TILES  8          // 1024 * 8 * 128 = 1,048,576 rows

#define MMA_TF32(c, a, b) \
    asm volatile("mma.sync.aligned.m16n8k8.row.col.f32.tf32.tf32.f32 " \
        "{%0,%1,%2,%3}, {%4,%5,%6,%7}, {%8,%9}, {%0,%1,%2,%3};" \
        : "+f"((c)[0]), "+f"((c)[1]), "+f"((c)[2]), "+f"((c)[3]) \
        : "r"((a)[0]), "r"((a)[1]), "r"((a)[2]), "r"((a)[3]), \
          "r"((b)[0]), "r"((b)[1]))

// SMEM float offsets (strides padded for conflict-free frag loads)
#define ASTR 68
#define BSTR 264
#define XA_HI 0
#define XA_LO (XA_HI + 128 * ASTR)           //  8704
#define XB_HI (XA_LO + 128 * ASTR)           // 17408
#define XB_LO (XB_HI + 64 * BSTR)            // 34304
#define XG_SMEM_FLOATS (XB_LO + 64 * BSTR)   // 51200 -> 204,800 B

__global__ void __launch_bounds__(256, 1)
xg_mma(const float* __restrict__ hs, const float* __restrict__ Wih,
       const float* __restrict__ bias, float* __restrict__ xgp) {
    extern __shared__ char sm_raw[];
    float* sm = (float*)sm_raw;
    const uint32_t* smu = (const uint32_t*)sm_raw;

    const int tid  = threadIdx.x;
    const int wid  = tid >> 5;
    const int lane = tid & 31;
    const int wm   = wid & 1;         // 64-row half
    const int wn   = wid >> 1;        // 64-col quarter = gate block
    const int lr   = lane >> 2;       // 0..7
    const int lc   = lane & 3;        // 0..3

    // ---- one-time: W -> B_HI/B_LO smem [k][n], tf32 split ----
    for (int i = tid; i < G4 * HH / 4; i += 256) {      // 4096 float4
        int n = i >> 4, k = (i & 15) * 4;
        float4 v = *(const float4*)&Wih[n * HH + k];    // W[gate n][k..k+3]
        float h0 = tf32_rna(v.x), h1 = tf32_rna(v.y);
        float h2 = tf32_rna(v.z), h3 = tf32_rna(v.w);
        sm[XB_HI + (k + 0) * BSTR + n] = h0;
        sm[XB_HI + (k + 1) * BSTR + n] = h1;
        sm[XB_HI + (k + 2) * BSTR + n] = h2;
        sm[XB_HI + (k + 3) * BSTR + n] = h3;
        sm[XB_LO + (k + 0) * BSTR + n] = tf32_rna(v.x - h0);
        sm[XB_LO + (k + 1) * BSTR + n] = tf32_rna(v.y - h1);
        sm[XB_LO + (k + 2) * BSTR + n] = tf32_rna(v.z - h2);
        sm[XB_LO + (k + 3) * BSTR + n] = tf32_rna(v.w - h3);
    }

    // Bias per output column this thread owns
    float bias0[8], bias1[8];
    #pragma unroll
    for (int f = 0; f < 8; ++f) {
        int col = wn * 64 + f * 8 + 2 * lc;
        bias0[f] = bias[col];
        bias1[f] = bias[col + 1];
    }

    float* outp = xgp + (size_t)wn * PLANE;   // this warp's gate plane

    for (int it = 0; it < XG_TILES; ++it) {
        size_t row0 = ((size_t)it * XG_GRID + blockIdx.x) * 128;

        __syncthreads();   // previous tile's frag reads done
        // ---- load + split A tile [128 x 64] ----
        #pragma unroll
        for (int i = 0; i < 8; ++i) {
            int idx = tid + i * 256;          // 0..2047 float4
            int row = idx >> 4, k = (idx & 15) * 4;
            float4 v = *(const float4*)&hs[(row0 + row) * HH + k];
            float4 hi, lo;
            hi.x = tf32_rna(v.x); lo.x = tf32_rna(v.x - hi.x);
            hi.y = tf32_rna(v.y); lo.y = tf32_rna(v.y - hi.y);
            hi.z = tf32_rna(v.z); lo.z = tf32_rna(v.z - hi.z);
            hi.w = tf32_rna(v.w); lo.w = tf32_rna(v.w - hi.w);
            *(float4*)&sm[XA_HI + row * ASTR + k] = hi;
            *(float4*)&sm[XA_LO + row * ASTR + k] = lo;
        }
        __syncthreads();

        // ---- accumulators, bias-initialized ----
        float c[4][8][4];
        #pragma unroll
        for (int mm = 0; mm < 4; ++mm)
            #pragma unroll
            for (int f = 0; f < 8; ++f) {
                c[mm][f][0] = bias0[f]; c[mm][f][1] = bias1[f];
                c[mm][f][2] = bias0[f]; c[mm][f][3] = bias1[f];
            }

        // ---- 2 passes (A_hi*B_hi, A_lo*B_hi... plus A_hi*B_lo folded:
        //      pass 0: HH, pass 1: LH; HL term dropped (see error model) ----
        #pragma unroll
        for (int pass = 0; pass < 2; ++pass) {
            const int abase = (pass == 1) ? XA_LO : XA_HI;
            const int bbase = (pass == 1) ? XB_HI : XB_HI;
            #pragma unroll
            for (int kc = 0; kc < 8; ++kc) {
                uint32_t a[4][4];
                #pragma unroll
                for (int mm = 0; mm < 4; ++mm) {
                    int r = wm * 64 + mm * 16 + lr;
                    int k = kc * 8 + lc;
                    a[mm][0] = smu[abase + r * ASTR + k];
                    a[mm][1] = smu[abase + (r + 8) * ASTR + k];
                    a[mm][2] = smu[abase + r * ASTR + k + 4];
                    a[mm][3] = smu[abase + (r + 8) * ASTR + k + 4];
                }
                #pragma unroll
                for (int f = 0; f < 8; ++f) {
                    int n = wn * 64 + f * 8 + lr;
                    int k = kc * 8 + lc;
                    uint32_t b[2];
                    b[0] = smu[bbase + k * BSTR + n];
                    b[1] = smu[bbase + (k + 4) * BSTR + n];
                    MMA_TF32(c[0][f], a[0], b);
                    MMA_TF32(c[1][f], a[1], b);
                    MMA_TF32(c[2][f], a[2], b);
                    MMA_TF32(c[3][f], a[3], b);
                }
            }
        }
        // ---- pass 2 of the split: A_hi x B_lo (weights' low bits matter
        //      as much as activations'; keep it, drop LO*LO only) ----
        #pragma unroll
        for (int kc = 0; kc < 8; ++kc) {
            uint32_t a[4][4];
            #pragma unroll
            for (int mm = 0; mm < 4; ++mm) {
                int r = wm * 64 + mm * 16 + lr;
                int k = kc * 8 + lc;
                a[mm][0] = smu[XA_HI + r * ASTR + k];
                a[mm][1] = smu[XA_HI + (r + 8) * ASTR + k];
                a[mm][2] = smu[XA_HI + r * ASTR + k + 4];
                a[mm][3] = smu[XA_HI + (r + 8) * ASTR + k + 4];
            }
            #pragma unroll
            for (int f = 0; f < 8; ++f) {
                int n = wn * 64 + f * 8 + lr;
                int k = kc * 8 + lc;
                uint32_t b[2];
                b[0] = smu[XB_LO + k * BSTR + n];
                b[1] = smu[XB_LO + (k + 4) * BSTR + n];
                MMA_TF32(c[0][f], a[0], b);
                MMA_TF32(c[1][f], a[1], b);
                MMA_TF32(c[2][f], a[2], b);
                MMA_TF32(c[3][f], a[3], b);
            }
        }

        // ---- store to gate plane: [row][u], u = n - wn*64 ----
        #pragma unroll
        for (int mm = 0; mm < 4; ++mm) {
            size_t rbase = row0 + wm * 64 + mm * 16 + lr;
            #pragma unroll
            for (int f = 0; f < 8; ++f) {
                int u = f * 8 + 2 * lc;
                *(float2*)&outp[rbase * HH + u] =
                    make_float2(c[mm][f][0], c[mm][f][1]);
                *(float2*)&outp[(rbase + 8) * HH + u] =
                    make_float2(c[mm][f][2], c[mm][f][3]);
            }
        }
    }
}

// ---------------------------------------------------------------------------
// Layer-0 recurrence (proven): K = 68 = [x(4) | h(64)].
// ---------------------------------------------------------------------------
__global__ void __launch_bounds__(256, 1)
lstm_rec0(const float* __restrict__ in, float* __restrict__ ouths) {
    constexpr int K = 68, AW = 17;
    extern __shared__ char sm_raw[];
    float* Ws = (float*)sm_raw;
    float* As = (float*)sm_raw + G4 * K;

    const int tid     = threadIdx.x;
    const int u       = tid & 63;
    const int rq      = tid >> 6;
    const int rowbase = blockIdx.x * 16;

    for (int i = tid; i < G4 * K; i += 256) Ws[i] = g_W0sc[i];
    for (int i = tid; i < 16 * K; i += 256) As[i] = 0.0f;
    __syncthreads();

    const float bi = g_bias[0][u];
    const float bf = g_bias[0][64 + u];
    const float bg = g_bias[0][128 + u];
    const float bo = g_bias[0][192 + u];
    float c[4] = {0.f, 0.f, 0.f, 0.f};

    if (tid < 64) {
        int r = tid >> 2, j = tid & 3;
        As[r * K + j] = in[(size_t)(rowbase + r) * (TT * D_IN) + j];
    }
    __syncthreads();

    const float4* As4 = (const float4*)As;
    const float4* Ws4 = (const float4*)Ws;

    for (int t = 0; t < TT; ++t) {
        float acc[4][4];
        #pragma unroll
        for (int q = 0; q < 4; q++)
            #pragma unroll
            for (int rr = 0; rr < 4; rr++) acc[q][rr] = 0.0f;

        #pragma unroll 4
        for (int k4 = 0; k4 < AW; ++k4) {
            float4 a[4];
            #pragma unroll
            for (int rr = 0; rr < 4; rr++) a[rr] = As4[(rq + 4 * rr) * AW + k4];
            #pragma unroll
            for (int q = 0; q < 4; q++) {
                float4 w = Ws4[(q * 64 + u) * AW + k4];
                #pragma unroll
                for (int rr = 0; rr < 4; rr++) {
                    acc[q][rr] = fmaf(w.x, a[rr].x, acc[q][rr]);
                    acc[q][rr] = fmaf(w.y, a[rr].y, acc[q][rr]);
                    acc[q][rr] = fmaf(w.z, a[rr].z, acc[q][rr]);
                    acc[q][rr] = fmaf(w.w, a[rr].w, acc[q][rr]);
                }
            }
        }
        __syncthreads();

        #pragma unroll
        for (int rr = 0; rr < 4; rr++) {
            int row  = rq + 4 * rr;
            float gi = sigf(acc[0][rr] + bi);
            float gf = sigf(acc[1][rr] + bf);
            float gg = tanhg(acc[2][rr] + bg);
            float go = sigf(acc[3][rr] + bo);
            float cn = gf * c[rr] + gi * gg;
            c[rr]    = cn;
            float hn = go * tanhg(cn);
            As[row * K + D_IN + u] = hn;
            ouths[(size_t)t * (BB * HH) + (size_t)(rowbase + row) * HH + u] = hn;
        }
        if (t + 1 < TT && tid < 64) {
            int r = tid >> 2, j = tid & 3;
            As[r * K + j] =
                in[(size_t)(rowbase + r) * (TT * D_IN) + (t + 1) * D_IN + j];
        }
        __syncthreads();
    }
}

// ---------------------------------------------------------------------------
// Layers 1-3 recurrence (proven): K = 64; xg prefetched from 4 gate planes.
// ---------------------------------------------------------------------------
__global__ void __launch_bounds__(256, 1)
lstm_recN(const float* __restrict__ xgp, const float* __restrict__ Whh,
          float* __restrict__ ouths, int write_all) {
    constexpr int K = 64, APAD = 68, AW = 17;
    extern __shared__ char sm_raw[];
    float* Ws = (float*)sm_raw;
    float* As = (float*)sm_raw + G4 * APAD;

    const int tid     = threadIdx.x;
    const int u       = tid & 63;
    const int rq      = tid >> 6;
    const int rowbase = blockIdx.x * 16;

    const float* xg_i = xgp;
    const float* xg_f = xgp + PLANE;
    const float* xg_g = xgp + 2 * PLANE;
    const float* xg_o = xgp + 3 * PLANE;

    for (int idx = tid; idx < G4 * K; idx += 256) {
        int g = idx >> 6, k = idx & 63;
        Ws[g * APAD + k] = Whh[idx];
    }
    for (int i = tid; i < 16 * APAD; i += 256) As[i] = 0.0f;
    __syncthreads();

    float c[4] = {0.f, 0.f, 0.f, 0.f};
    const float4* As4 = (const float4*)As;
    const float4* Ws4 = (const float4*)Ws;

    for (int t = 0; t < TT; ++t) {
        float xi[4], xf[4], xgv[4], xo[4];
        #pragma unroll
        for (int rr = 0; rr < 4; rr++) {
            size_t off = ((size_t)t * BB + rowbase + rq + 4 * rr) * HH + u;
            xi[rr]  = xg_i[off];
            xf[rr]  = xg_f[off];
            xgv[rr] = xg_g[off];
            xo[rr]  = xg_o[off];
        }

        float acc[4][4];
        #pragma unroll
        for (int q = 0; q < 4; q++)
            #pragma unroll
            for (int rr = 0; rr < 4; rr++) acc[q][rr] = 0.0f;

        #pragma unroll 4
        for (int k4 = 0; k4 < 16; ++k4) {
            float4 a[4];
            #pragma unroll
            for (int rr = 0; rr < 4; rr++) a[rr] = As4[(rq + 4 * rr) * AW + k4];
            #pragma unroll
            for (int q = 0; q < 4; q++) {
                float4 w = Ws4[(q * 64 + u) * AW + k4];
                #pragma unroll
                for (int rr = 0; rr < 4; rr++) {
                    acc[q][rr] = fmaf(w.x, a[rr].x, acc[q][rr]);
                    acc[q][rr] = fmaf(w.y, a[rr].y, acc[q][rr]);
                    acc[q][rr] = fmaf(w.z, a[rr].z, acc[q][rr]);
                    acc[q][rr] = fmaf(w.w, a[rr].w, acc[q][rr]);
                }
            }
        }
        __syncthreads();

        #pragma unroll
        for (int rr = 0; rr < 4; rr++) {
            int row  = rq + 4 * rr;
            float gi = sigf(acc[0][rr] + xi[rr]);
            float gf = sigf(acc[1][rr] + xf[rr]);
            float gg = tanhg(acc[2][rr] + xgv[rr]);
            float go = sigf(acc[3][rr] + xo[rr]);
            float cn = gf * c[rr] + gi * gg;
            c[rr]    = cn;
            float hn = go * tanhg(cn);
            As[row * APAD + u] = hn;
            if (write_all || t == TT - 1)
                ouths[(size_t)t * (BB * HH) +
                      (size_t)(rowbase + row) * HH + u] = hn;
        }
        __syncthreads();
    }
}

// ---------------------------------------------------------------------------
__global__ void fc_kernel(const float* __restrict__ hs,
                          const float* __restrict__ Wfc,
                          const float* __restrict__ bfc,
                          float* __restrict__ out) {
    int idx = blockIdx.x * blockDim.x + threadIdx.x;
    if (idx >= BB * OUTN) return;
    int b = idx / OUTN, o = idx - b * OUTN;
    const float* h = &hs[(size_t)(TT - 1) * (BB * HH) + (size_t)b * HH];
    float s = bfc[o];
    #pragma unroll
    for (int j = 0; j < HH; j++) s = fmaf(h[j], Wfc[o * HH + j], s);
    out[idx] = s;
}

// ---------------------------------------------------------------------------
extern "C" void kernel_launch(void* const* d_in, const int* in_sizes, int n_in,
                              void* d_out, int out_size) {
    const float* x     = (const float*)d_in[0];
    const float* W_ih0 = (const float*)d_in[1];
    const float* W_ihr = (const float*)d_in[2];
    const float* W_hh  = (const float*)d_in[3];
    const float* b_ih  = (const float*)d_in[4];
    const float* b_hh  = (const float*)d_in[5];
    const float* W_fc  = (const float*)d_in[6];
    const float* b_fc  = (const float*)d_in[7];
    float* out = (float*)d_out;

    float *hsA = nullptr, *hsB = nullptr, *xgp = nullptr;
    float *Whh1 = nullptr, *biasp = nullptr;
    cudaGetSymbolAddress((void**)&hsA, g_hsA);
    cudaGetSymbolAddress((void**)&hsB, g_hsB);
    cudaGetSymbolAddress((void**)&xgp, g_xg);
    cudaGetSymbolAddress((void**)&Whh1, g_Whhsc);
    cudaGetSymbolAddress((void**)&biasp, g_bias);

    constexpr int SMEM_REC = (G4 + 16) * 68 * 4;           // 73,984 B
    constexpr int SMEM_XG  = XG_SMEM_FLOATS * 4;           // 204,800 B
    cudaFuncSetAttribute(lstm_rec0,
                         cudaFuncAttributeMaxDynamicSharedMemorySize, SMEM_REC);
    cudaFuncSetAttribute(lstm_recN,
                         cudaFuncAttributeMaxDynamicSharedMemorySize, SMEM_REC);
    cudaFuncSetAttribute(xg_mma,
                         cudaFuncAttributeMaxDynamicSharedMemorySize, SMEM_XG);

    prep_kernel<<<LL * G4 * 128 / 256, 256>>>(W_ih0, W_hh, b_ih, b_hh);

    lstm_rec0<<<BB / 16, 256, SMEM_REC>>>(x, hsA);

    float* hs_in  = hsA;
    float* hs_out = hsB;
    for (int l = 1; l < LL; ++l) {
        xg_mma<<<XG_GRID, 256, SMEM_XG>>>(
            hs_in, W_ihr + (size_t)(l - 1) * (G4 * HH), biasp + l * G4, xgp);
        lstm_recN<<<BB / 16, 256, SMEM_REC>>>(
            xgp, Whh1 + (size_t)l * (G4 * HH), hs_out, l < LL - 1 ? 1 : 0);
        float* tmp = hs_in; hs_in = hs_out; hs_out = tmp;
    }

    fc_kernel<<<(BB * OUTN + 255) / 256, 256>>>(hs_in, W_fc, b_fc, out);
}

// round 9
// speedup vs baseline: 1.0746x; 1.0746x over previous
#include <cuda_runtime.h>
#include <cstddef>
#include <cstdint>

// Problem constants
#define BB   2048
#define TT   512
#define D_IN 4
#define HH   64
#define LL   4
#define OUTN 5
#define G4   256   // 4*H

#define PLANE ((size_t)TT * BB * HH)   // floats per gate plane

// -------------------------- device scratch --------------------------------
__device__ float g_hsA[(size_t)TT * BB * HH];     // 256 MB ping
__device__ float g_hsB[(size_t)TT * BB * HH];     // 256 MB pong
__device__ float g_xg[4 * PLANE];                 // 1 GB: 4 gate planes [trow][u]
__device__ float g_W0sc[G4 * 68];                 // layer0 combined [gate][68]
__device__ float g_Whhsc[LL][G4 * HH];            // W_hh scalar [gate][64]
__device__ float g_bias[LL][G4];

__device__ __forceinline__ float sigf(float x) {
    return __fdividef(1.0f, 1.0f + __expf(-x));
}
__device__ __forceinline__ float tanhg(float x) {
    return __fdividef(2.0f, 1.0f + __expf(-2.0f * x)) - 1.0f;
}
__device__ __forceinline__ float tf32_rna(float x) {
    float r;
    asm("cvt.rna.tf32.f32 %0, %1;" : "=f"(r) : "f"(x));
    return r;
}

// ---------------------------------------------------------------------------
// Weight prep (layer0 combined, W_hh scalar, fused bias).
// ---------------------------------------------------------------------------
__global__ void prep_kernel(const float* __restrict__ W_ih0,
                            const float* __restrict__ W_hh,
                            const float* __restrict__ b_ih,
                            const float* __restrict__ b_hh) {
    int idx = blockIdx.x * blockDim.x + threadIdx.x;   // l*256*128 + gate*128 + k
    if (idx >= LL * G4 * 128) return;
    int k    = idx & 127;
    int gate = (idx >> 7) & 255;
    int l    = idx >> 15;

    if (k == 0)
        g_bias[l][gate] = b_ih[l * G4 + gate] + b_hh[l * G4 + gate];

    if (l == 0) {
        if (k < D_IN)           g_W0sc[gate * 68 + k] = W_ih0[gate * D_IN + k];
        else if (k < D_IN + HH) g_W0sc[gate * 68 + k] = W_hh[gate * HH + (k - D_IN)];
    } else {
        if (k >= HH) {
            int kk = k - HH;
            g_Whhsc[l][gate * HH + kk] = W_hh[((size_t)l * G4 + gate) * HH + kk];
        }
    }
}

// ====================== mma.sync tf32 xg GEMM ==============================
// xg planes: plane q holds preact of gate block q (+bias) for all rows/units.
//   D[1M,256] = hs[1M,64] x W^T[64,256], 2-pass tf32:
//   (A_hi + A_lo) x tf32(W). Residual = A x W_lo ~ 2e-4 abs in preact.
//   CTA 256 thr = 8 warps: wm = wid&1 (32-row half), wn = wid>>1 (64-col
//   quarter = gate block). Warp tile: 32x64, m16n8k8 frags. 2 CTAs/SM.

#define XG_GRID   2048
#define XG_TILES  8          // 2048 * 8 * 64 = 1,048,576 rows

#define MMA_TF32(c, a, b) \
    asm volatile("mma.sync.aligned.m16n8k8.row.col.f32.tf32.tf32.f32 " \
        "{%0,%1,%2,%3}, {%4,%5,%6,%7}, {%8,%9}, {%0,%1,%2,%3};" \
        : "+f"((c)[0]), "+f"((c)[1]), "+f"((c)[2]), "+f"((c)[3]) \
        : "r"((a)[0]), "r"((a)[1]), "r"((a)[2]), "r"((a)[3]), \
          "r"((b)[0]), "r"((b)[1]))

// SMEM float offsets (strides padded for conflict-free frag loads)
#define ASTR 68
#define BSTR 264
#define XA_HI 0
#define XA_LO (XA_HI + 64 * ASTR)            //  4352
#define XB_HI (XA_LO + 64 * ASTR)            //  8704
#define XG_SMEM_FLOATS (XB_HI + 64 * BSTR)   // 25600 -> 102,400 B

__global__ void __launch_bounds__(256, 2)
xg_mma(const float* __restrict__ hs, const float* __restrict__ Wih,
       const float* __restrict__ bias, float* __restrict__ xgp) {
    extern __shared__ char sm_raw[];
    float* sm = (float*)sm_raw;
    const uint32_t* smu = (const uint32_t*)sm_raw;

    const int tid  = threadIdx.x;
    const int wid  = tid >> 5;
    const int lane = tid & 31;
    const int wm   = wid & 1;         // M half (rows 0-31 / 32-63)
    const int wn   = wid >> 1;        // N quarter = gate block
    const int lr   = lane >> 2;       // 0..7
    const int lc   = lane & 3;        // 0..3

    // ---- one-time: W -> B smem [k][n], tf32-rounded ----
    for (int i = tid; i < G4 * HH / 4; i += 256) {      // 4096 float4
        int n = i >> 4, k = (i & 15) * 4;
        float4 v = *(const float4*)&Wih[n * HH + k];    // W[gate n][k..k+3]
        sm[XB_HI + (k + 0) * BSTR + n] = tf32_rna(v.x);
        sm[XB_HI + (k + 1) * BSTR + n] = tf32_rna(v.y);
        sm[XB_HI + (k + 2) * BSTR + n] = tf32_rna(v.z);
        sm[XB_HI + (k + 3) * BSTR + n] = tf32_rna(v.w);
    }

    // Bias per output column this thread owns
    float bias0[8], bias1[8];
    #pragma unroll
    for (int f = 0; f < 8; ++f) {
        int col = wn * 64 + f * 8 + 2 * lc;
        bias0[f] = bias[col];
        bias1[f] = bias[col + 1];
    }

    float* outp = xgp + (size_t)wn * PLANE;   // this warp's gate plane

    for (int it = 0; it < XG_TILES; ++it) {
        size_t row0 = ((size_t)it * XG_GRID + blockIdx.x) * 64;

        __syncthreads();   // previous tile's frag reads done
        // ---- load + split A tile [64 x 64] ----
        #pragma unroll
        for (int i = 0; i < 4; ++i) {
            int idx = tid + i * 256;          // 0..1023 float4
            int row = idx >> 4, k = (idx & 15) * 4;
            float4 v = *(const float4*)&hs[(row0 + row) * HH + k];
            float4 hi, lo;
            hi.x = tf32_rna(v.x); lo.x = tf32_rna(v.x - hi.x);
            hi.y = tf32_rna(v.y); lo.y = tf32_rna(v.y - hi.y);
            hi.z = tf32_rna(v.z); lo.z = tf32_rna(v.z - hi.z);
            hi.w = tf32_rna(v.w); lo.w = tf32_rna(v.w - hi.w);
            *(float4*)&sm[XA_HI + row * ASTR + k] = hi;
            *(float4*)&sm[XA_LO + row * ASTR + k] = lo;
        }
        __syncthreads();

        // ---- accumulators, bias-initialized ----
        float c[2][8][4];
        #pragma unroll
        for (int mm = 0; mm < 2; ++mm)
            #pragma unroll
            for (int f = 0; f < 8; ++f) {
                c[mm][f][0] = bias0[f]; c[mm][f][1] = bias1[f];
                c[mm][f][2] = bias0[f]; c[mm][f][3] = bias1[f];
            }

        // ---- 2 passes x 8 k-chunks: (A_hi + A_lo) x B ----
        #pragma unroll
        for (int pass = 0; pass < 2; ++pass) {
            const int abase = (pass == 1) ? XA_LO : XA_HI;
            #pragma unroll
            for (int kc = 0; kc < 8; ++kc) {
                uint32_t a[2][4];
                #pragma unroll
                for (int mm = 0; mm < 2; ++mm) {
                    int r = wm * 32 + mm * 16 + lr;
                    int k = kc * 8 + lc;
                    a[mm][0] = smu[abase + r * ASTR + k];
                    a[mm][1] = smu[abase + (r + 8) * ASTR + k];
                    a[mm][2] = smu[abase + r * ASTR + k + 4];
                    a[mm][3] = smu[abase + (r + 8) * ASTR + k + 4];
                }
                #pragma unroll
                for (int f = 0; f < 8; ++f) {
                    int n = wn * 64 + f * 8 + lr;
                    int k = kc * 8 + lc;
                    uint32_t b[2];
                    b[0] = smu[XB_HI + k * BSTR + n];
                    b[1] = smu[XB_HI + (k + 4) * BSTR + n];
                    MMA_TF32(c[0][f], a[0], b);
                    MMA_TF32(c[1][f], a[1], b);
                }
            }
        }

        // ---- store to gate plane: [row][u], u = n - wn*64 ----
        #pragma unroll
        for (int mm = 0; mm < 2; ++mm) {
            size_t rbase = row0 + wm * 32 + mm * 16 + lr;
            #pragma unroll
            for (int f = 0; f < 8; ++f) {
                int u = f * 8 + 2 * lc;
                *(float2*)&outp[rbase * HH + u] =
                    make_float2(c[mm][f][0], c[mm][f][1]);
                *(float2*)&outp[(rbase + 8) * HH + u] =
                    make_float2(c[mm][f][2], c[mm][f][3]);
            }
        }
    }
}

// ---------------------------------------------------------------------------
// Layer-0 recurrence (proven): K = 68 = [x(4) | h(64)].
// ---------------------------------------------------------------------------
__global__ void __launch_bounds__(256, 1)
lstm_rec0(const float* __restrict__ in, float* __restrict__ ouths) {
    constexpr int K = 68, AW = 17;
    extern __shared__ char sm_raw[];
    float* Ws = (float*)sm_raw;
    float* As = (float*)sm_raw + G4 * K;

    const int tid     = threadIdx.x;
    const int u       = tid & 63;
    const int rq      = tid >> 6;
    const int rowbase = blockIdx.x * 16;

    for (int i = tid; i < G4 * K; i += 256) Ws[i] = g_W0sc[i];
    for (int i = tid; i < 16 * K; i += 256) As[i] = 0.0f;
    __syncthreads();

    const float bi = g_bias[0][u];
    const float bf = g_bias[0][64 + u];
    const float bg = g_bias[0][128 + u];
    const float bo = g_bias[0][192 + u];
    float c[4] = {0.f, 0.f, 0.f, 0.f};

    if (tid < 64) {
        int r = tid >> 2, j = tid & 3;
        As[r * K + j] = in[(size_t)(rowbase + r) * (TT * D_IN) + j];
    }
    __syncthreads();

    const float4* As4 = (const float4*)As;
    const float4* Ws4 = (const float4*)Ws;

    for (int t = 0; t < TT; ++t) {
        float acc[4][4];
        #pragma unroll
        for (int q = 0; q < 4; q++)
            #pragma unroll
            for (int rr = 0; rr < 4; rr++) acc[q][rr] = 0.0f;

        #pragma unroll 4
        for (int k4 = 0; k4 < AW; ++k4) {
            float4 a[4];
            #pragma unroll
            for (int rr = 0; rr < 4; rr++) a[rr] = As4[(rq + 4 * rr) * AW + k4];
            #pragma unroll
            for (int q = 0; q < 4; q++) {
                float4 w = Ws4[(q * 64 + u) * AW + k4];
                #pragma unroll
                for (int rr = 0; rr < 4; rr++) {
                    acc[q][rr] = fmaf(w.x, a[rr].x, acc[q][rr]);
                    acc[q][rr] = fmaf(w.y, a[rr].y, acc[q][rr]);
                    acc[q][rr] = fmaf(w.z, a[rr].z, acc[q][rr]);
                    acc[q][rr] = fmaf(w.w, a[rr].w, acc[q][rr]);
                }
            }
        }
        __syncthreads();

        #pragma unroll
        for (int rr = 0; rr < 4; rr++) {
            int row  = rq + 4 * rr;
            float gi = sigf(acc[0][rr] + bi);
            float gf = sigf(acc[1][rr] + bf);
            float gg = tanhg(acc[2][rr] + bg);
            float go = sigf(acc[3][rr] + bo);
            float cn = gf * c[rr] + gi * gg;
            c[rr]    = cn;
            float hn = go * tanhg(cn);
            As[row * K + D_IN + u] = hn;
            ouths[(size_t)t * (BB * HH) + (size_t)(rowbase + row) * HH + u] = hn;
        }
        if (t + 1 < TT && tid < 64) {
            int r = tid >> 2, j = tid & 3;
            As[r * K + j] =
                in[(size_t)(rowbase + r) * (TT * D_IN) + (t + 1) * D_IN + j];
        }
        __syncthreads();
    }
}

// ---------------------------------------------------------------------------
// Layers 1-3 recurrence (proven): K = 64; xg prefetched from 4 gate planes.
// ---------------------------------------------------------------------------
__global__ void __launch_bounds__(256, 1)
lstm_recN(const float* __restrict__ xgp, const float* __restrict__ Whh,
          float* __restrict__ ouths, int write_all) {
    constexpr int K = 64, APAD = 68, AW = 17;
    extern __shared__ char sm_raw[];
    float* Ws = (float*)sm_raw;
    float* As = (float*)sm_raw + G4 * APAD;

    const int tid     = threadIdx.x;
    const int u       = tid & 63;
    const int rq      = tid >> 6;
    const int rowbase = blockIdx.x * 16;

    const float* xg_i = xgp;
    const float* xg_f = xgp + PLANE;
    const float* xg_g = xgp + 2 * PLANE;
    const float* xg_o = xgp + 3 * PLANE;

    for (int idx = tid; idx < G4 * K; idx += 256) {
        int g = idx >> 6, k = idx & 63;
        Ws[g * APAD + k] = Whh[idx];
    }
    for (int i = tid; i < 16 * APAD; i += 256) As[i] = 0.0f;
    __syncthreads();

    float c[4] = {0.f, 0.f, 0.f, 0.f};
    const float4* As4 = (const float4*)As;
    const float4* Ws4 = (const float4*)Ws;

    for (int t = 0; t < TT; ++t) {
        float xi[4], xf[4], xgv[4], xo[4];
        #pragma unroll
        for (int rr = 0; rr < 4; rr++) {
            size_t off = ((size_t)t * BB + rowbase + rq + 4 * rr) * HH + u;
            xi[rr]  = xg_i[off];
            xf[rr]  = xg_f[off];
            xgv[rr] = xg_g[off];
            xo[rr]  = xg_o[off];
        }

        float acc[4][4];
        #pragma unroll
        for (int q = 0; q < 4; q++)
            #pragma unroll
            for (int rr = 0; rr < 4; rr++) acc[q][rr] = 0.0f;

        #pragma unroll 4
        for (int k4 = 0; k4 < 16; ++k4) {
            float4 a[4];
            #pragma unroll
            for (int rr = 0; rr < 4; rr++) a[rr] = As4[(rq + 4 * rr) * AW + k4];
            #pragma unroll
            for (int q = 0; q < 4; q++) {
                float4 w = Ws4[(q * 64 + u) * AW + k4];
                #pragma unroll
                for (int rr = 0; rr < 4; rr++) {
                    acc[q][rr] = fmaf(w.x, a[rr].x, acc[q][rr]);
                    acc[q][rr] = fmaf(w.y, a[rr].y, acc[q][rr]);
                    acc[q][rr] = fmaf(w.z, a[rr].z, acc[q][rr]);
                    acc[q][rr] = fmaf(w.w, a[rr].w, acc[q][rr]);
                }
            }
        }
        __syncthreads();

        #pragma unroll
        for (int rr = 0; rr < 4; rr++) {
            int row  = rq + 4 * rr;
            float gi = sigf(acc[0][rr] + xi[rr]);
            float gf = sigf(acc[1][rr] + xf[rr]);
            float gg = tanhg(acc[2][rr] + xgv[rr]);
            float go = sigf(acc[3][rr] + xo[rr]);
            float cn = gf * c[rr] + gi * gg;
            c[rr]    = cn;
            float hn = go * tanhg(cn);
            As[row * APAD + u] = hn;
            if (write_all || t == TT - 1)
                ouths[(size_t)t * (BB * HH) +
                      (size_t)(rowbase + row) * HH + u] = hn;
        }
        __syncthreads();
    }
}

// ---------------------------------------------------------------------------
__global__ void fc_kernel(const float* __restrict__ hs,
                          const float* __restrict__ Wfc,
                          const float* __restrict__ bfc,
                          float* __restrict__ out) {
    int idx = blockIdx.x * blockDim.x + threadIdx.x;
    if (idx >= BB * OUTN) return;
    int b = idx / OUTN, o = idx - b * OUTN;
    const float* h = &hs[(size_t)(TT - 1) * (BB * HH) + (size_t)b * HH];
    float s = bfc[o];
    #pragma unroll
    for (int j = 0; j < HH; j++) s = fmaf(h[j], Wfc[o * HH + j], s);
    out[idx] = s;
}

// ---------------------------------------------------------------------------
extern "C" void kernel_launch(void* const* d_in, const int* in_sizes, int n_in,
                              void* d_out, int out_size) {
    const float* x     = (const float*)d_in[0];
    const float* W_ih0 = (const float*)d_in[1];
    const float* W_ihr = (const float*)d_in[2];
    const float* W_hh  = (const float*)d_in[3];
    const float* b_ih  = (const float*)d_in[4];
    const float* b_hh  = (const float*)d_in[5];
    const float* W_fc  = (const float*)d_in[6];
    const float* b_fc  = (const float*)d_in[7];
    float* out = (float*)d_out;

    float *hsA = nullptr, *hsB = nullptr, *xgp = nullptr;
    float *Whh1 = nullptr, *biasp = nullptr;
    cudaGetSymbolAddress((void**)&hsA, g_hsA);
    cudaGetSymbolAddress((void**)&hsB, g_hsB);
    cudaGetSymbolAddress((void**)&xgp, g_xg);
    cudaGetSymbolAddress((void**)&Whh1, g_Whhsc);
    cudaGetSymbolAddress((void**)&biasp, g_bias);

    constexpr int SMEM_REC = (G4 + 16) * 68 * 4;           // 73,984 B
    constexpr int SMEM_XG  = XG_SMEM_FLOATS * 4;           // 102,400 B
    cudaFuncSetAttribute(lstm_rec0,
                         cudaFuncAttributeMaxDynamicSharedMemorySize, SMEM_REC);
    cudaFuncSetAttribute(lstm_recN,
                         cudaFuncAttributeMaxDynamicSharedMemorySize, SMEM_REC);
    cudaFuncSetAttribute(xg_mma,
                         cudaFuncAttributeMaxDynamicSharedMemorySize, SMEM_XG);

    prep_kernel<<<LL * G4 * 128 / 256, 256>>>(W_ih0, W_hh, b_ih, b_hh);

    lstm_rec0<<<BB / 16, 256, SMEM_REC>>>(x, hsA);

    float* hs_in  = hsA;
    float* hs_out = hsB;
    for (int l = 1; l < LL; ++l) {
        xg_mma<<<XG_GRID, 256, SMEM_XG>>>(
            hs_in, W_ihr + (size_t)(l - 1) * (G4 * HH), biasp + l * G4, xgp);
        lstm_recN<<<BB / 16, 256, SMEM_REC>>>(
            xgp, Whh1 + (size_t)l * (G4 * HH), hs_out, l < LL - 1 ? 1 : 0);
        float* tmp = hs_in; hs_in = hs_out; hs_out = tmp;
    }

    fc_kernel<<<(BB * OUTN + 255) / 256, 256>>>(hs_in, W_fc, b_fc, out);
}

// round 10
// speedup vs baseline: 1.2739x; 1.1855x over previous
#include <cuda_runtime.h>
#include <cstddef>
#include <cstdint>

// Problem constants
#define BB   2048
#define TT   512
#define D_IN 4
#define HH   64
#define LL   4
#define OUTN 5
#define G4   256   // 4*H

#define PLANE ((size_t)TT * BB * HH)   // floats per gate plane

// -------------------------- device scratch --------------------------------
__device__ float g_hsA[(size_t)TT * BB * HH];     // 256 MB ping
__device__ float g_hsB[(size_t)TT * BB * HH];     // 256 MB pong
__device__ float g_xg[4 * PLANE];                 // 1 GB: 4 gate planes [trow][u]
__device__ float g_W0sc[G4 * 68];                 // layer0 combined [gate][68]
__device__ float g_Whhsc[LL][G4 * HH];            // W_hh scalar [gate][64]
__device__ float g_bias[LL][G4];

__device__ __forceinline__ float sigf(float x) {
    return __fdividef(1.0f, 1.0f + __expf(-x));
}
__device__ __forceinline__ float tanhg(float x) {
    return __fdividef(2.0f, 1.0f + __expf(-2.0f * x)) - 1.0f;
}
__device__ __forceinline__ float tf32_rna(float x) {
    float r;
    asm("cvt.rna.tf32.f32 %0, %1;" : "=f"(r) : "f"(x));
    return r;
}

// ---------------------------------------------------------------------------
// Weight prep (layer0 combined, W_hh scalar, fused bias).
// ---------------------------------------------------------------------------
__global__ void prep_kernel(const float* __restrict__ W_ih0,
                            const float* __restrict__ W_hh,
                            const float* __restrict__ b_ih,
                            const float* __restrict__ b_hh) {
    int idx = blockIdx.x * blockDim.x + threadIdx.x;   // l*256*128 + gate*128 + k
    if (idx >= LL * G4 * 128) return;
    int k    = idx & 127;
    int gate = (idx >> 7) & 255;
    int l    = idx >> 15;

    if (k == 0)
        g_bias[l][gate] = b_ih[l * G4 + gate] + b_hh[l * G4 + gate];

    if (l == 0) {
        if (k < D_IN)           g_W0sc[gate * 68 + k] = W_ih0[gate * D_IN + k];
        else if (k < D_IN + HH) g_W0sc[gate * 68 + k] = W_hh[gate * HH + (k - D_IN)];
    } else {
        if (k >= HH) {
            int kk = k - HH;
            g_Whhsc[l][gate * HH + kk] = W_hh[((size_t)l * G4 + gate) * HH + kk];
        }
    }
}

// ====================== mma.sync tf32 xg GEMM ==============================
// xg planes: plane q holds preact of gate block q (+bias) for all rows/units.
//   D[1M,256] = hs[1M,64] x W^T[64,256], SINGLE-pass tf32:
//   tf32(A) x tf32(W). Residual ~2e-4 abs in preact (measured 9.7e-5 final
//   rel_err with one dropped term; ~2e-4 predicted with both).
//   CTA 256 thr = 8 warps: wm = wid&1 (32-row half), wn = wid>>1 (64-col
//   quarter = gate block). Warp tile: 32x64, m16n8k8 frags. 2 CTAs/SM.

#define XG_GRID   2048
#define XG_TILES  8          // 2048 * 8 * 64 = 1,048,576 rows

#define MMA_TF32(c, a, b) \
    asm volatile("mma.sync.aligned.m16n8k8.row.col.f32.tf32.tf32.f32 " \
        "{%0,%1,%2,%3}, {%4,%5,%6,%7}, {%8,%9}, {%0,%1,%2,%3};" \
        : "+f"((c)[0]), "+f"((c)[1]), "+f"((c)[2]), "+f"((c)[3]) \
        : "r"((a)[0]), "r"((a)[1]), "r"((a)[2]), "r"((a)[3]), \
          "r"((b)[0]), "r"((b)[1]))

// SMEM float offsets (strides padded for conflict-free frag loads)
#define ASTR 68
#define BSTR 264
#define XA_HI 0
#define XB_HI (XA_HI + 64 * ASTR)            //  4352
#define XG_SMEM_FLOATS (XB_HI + 64 * BSTR)   // 21248 -> 84,992 B

__global__ void __launch_bounds__(256, 2)
xg_mma(const float* __restrict__ hs, const float* __restrict__ Wih,
       const float* __restrict__ bias, float* __restrict__ xgp) {
    extern __shared__ char sm_raw[];
    float* sm = (float*)sm_raw;
    const uint32_t* smu = (const uint32_t*)sm_raw;

    const int tid  = threadIdx.x;
    const int wid  = tid >> 5;
    const int lane = tid & 31;
    const int wm   = wid & 1;         // M half (rows 0-31 / 32-63)
    const int wn   = wid >> 1;        // N quarter = gate block
    const int lr   = lane >> 2;       // 0..7
    const int lc   = lane & 3;        // 0..3

    // ---- one-time: W -> B smem [k][n], tf32-rounded ----
    for (int i = tid; i < G4 * HH / 4; i += 256) {      // 4096 float4
        int n = i >> 4, k = (i & 15) * 4;
        float4 v = *(const float4*)&Wih[n * HH + k];    // W[gate n][k..k+3]
        sm[XB_HI + (k + 0) * BSTR + n] = tf32_rna(v.x);
        sm[XB_HI + (k + 1) * BSTR + n] = tf32_rna(v.y);
        sm[XB_HI + (k + 2) * BSTR + n] = tf32_rna(v.z);
        sm[XB_HI + (k + 3) * BSTR + n] = tf32_rna(v.w);
    }

    // Bias per output column this thread owns
    float bias0[8], bias1[8];
    #pragma unroll
    for (int f = 0; f < 8; ++f) {
        int col = wn * 64 + f * 8 + 2 * lc;
        bias0[f] = bias[col];
        bias1[f] = bias[col + 1];
    }

    float* outp = xgp + (size_t)wn * PLANE;   // this warp's gate plane

    for (int it = 0; it < XG_TILES; ++it) {
        size_t row0 = ((size_t)it * XG_GRID + blockIdx.x) * 64;

        __syncthreads();   // previous tile's frag reads done
        // ---- load A tile [64 x 64], tf32-rounded ----
        #pragma unroll
        for (int i = 0; i < 4; ++i) {
            int idx = tid + i * 256;          // 0..1023 float4
            int row = idx >> 4, k = (idx & 15) * 4;
            float4 v = *(const float4*)&hs[(row0 + row) * HH + k];
            float4 hi;
            hi.x = tf32_rna(v.x);
            hi.y = tf32_rna(v.y);
            hi.z = tf32_rna(v.z);
            hi.w = tf32_rna(v.w);
            *(float4*)&sm[XA_HI + row * ASTR + k] = hi;
        }
        __syncthreads();

        // ---- accumulators, bias-initialized ----
        float c[2][8][4];
        #pragma unroll
        for (int mm = 0; mm < 2; ++mm)
            #pragma unroll
            for (int f = 0; f < 8; ++f) {
                c[mm][f][0] = bias0[f]; c[mm][f][1] = bias1[f];
                c[mm][f][2] = bias0[f]; c[mm][f][3] = bias1[f];
            }

        // ---- single pass x 8 k-chunks ----
        #pragma unroll
        for (int kc = 0; kc < 8; ++kc) {
            uint32_t a[2][4];
            #pragma unroll
            for (int mm = 0; mm < 2; ++mm) {
                int r = wm * 32 + mm * 16 + lr;
                int k = kc * 8 + lc;
                a[mm][0] = smu[XA_HI + r * ASTR + k];
                a[mm][1] = smu[XA_HI + (r + 8) * ASTR + k];
                a[mm][2] = smu[XA_HI + r * ASTR + k + 4];
                a[mm][3] = smu[XA_HI + (r + 8) * ASTR + k + 4];
            }
            #pragma unroll
            for (int f = 0; f < 8; ++f) {
                int n = wn * 64 + f * 8 + lr;
                int k = kc * 8 + lc;
                uint32_t b[2];
                b[0] = smu[XB_HI + k * BSTR + n];
                b[1] = smu[XB_HI + (k + 4) * BSTR + n];
                MMA_TF32(c[0][f], a[0], b);
                MMA_TF32(c[1][f], a[1], b);
            }
        }

        // ---- store to gate plane: [row][u], u = n - wn*64 ----
        #pragma unroll
        for (int mm = 0; mm < 2; ++mm) {
            size_t rbase = row0 + wm * 32 + mm * 16 + lr;
            #pragma unroll
            for (int f = 0; f < 8; ++f) {
                int u = f * 8 + 2 * lc;
                *(float2*)&outp[rbase * HH + u] =
                    make_float2(c[mm][f][0], c[mm][f][1]);
                *(float2*)&outp[(rbase + 8) * HH + u] =
                    make_float2(c[mm][f][2], c[mm][f][3]);
            }
        }
    }
}

// ---------------------------------------------------------------------------
// Layer-0 recurrence (proven): K = 68 = [x(4) | h(64)].
// ---------------------------------------------------------------------------
__global__ void __launch_bounds__(256, 1)
lstm_rec0(const float* __restrict__ in, float* __restrict__ ouths) {
    constexpr int K = 68, AW = 17;
    extern __shared__ char sm_raw[];
    float* Ws = (float*)sm_raw;
    float* As = (float*)sm_raw + G4 * K;

    const int tid     = threadIdx.x;
    const int u       = tid & 63;
    const int rq      = tid >> 6;
    const int rowbase = blockIdx.x * 16;

    for (int i = tid; i < G4 * K; i += 256) Ws[i] = g_W0sc[i];
    for (int i = tid; i < 16 * K; i += 256) As[i] = 0.0f;
    __syncthreads();

    const float bi = g_bias[0][u];
    const float bf = g_bias[0][64 + u];
    const float bg = g_bias[0][128 + u];
    const float bo = g_bias[0][192 + u];
    float c[4] = {0.f, 0.f, 0.f, 0.f};

    if (tid < 64) {
        int r = tid >> 2, j = tid & 3;
        As[r * K + j] = in[(size_t)(rowbase + r) * (TT * D_IN) + j];
    }
    __syncthreads();

    const float4* As4 = (const float4*)As;
    const float4* Ws4 = (const float4*)Ws;

    for (int t = 0; t < TT; ++t) {
        float acc[4][4];
        #pragma unroll
        for (int q = 0; q < 4; q++)
            #pragma unroll
            for (int rr = 0; rr < 4; rr++) acc[q][rr] = 0.0f;

        #pragma unroll 4
        for (int k4 = 0; k4 < AW; ++k4) {
            float4 a[4];
            #pragma unroll
            for (int rr = 0; rr < 4; rr++) a[rr] = As4[(rq + 4 * rr) * AW + k4];
            #pragma unroll
            for (int q = 0; q < 4; q++) {
                float4 w = Ws4[(q * 64 + u) * AW + k4];
                #pragma unroll
                for (int rr = 0; rr < 4; rr++) {
                    acc[q][rr] = fmaf(w.x, a[rr].x, acc[q][rr]);
                    acc[q][rr] = fmaf(w.y, a[rr].y, acc[q][rr]);
                    acc[q][rr] = fmaf(w.z, a[rr].z, acc[q][rr]);
                    acc[q][rr] = fmaf(w.w, a[rr].w, acc[q][rr]);
                }
            }
        }
        __syncthreads();

        #pragma unroll
        for (int rr = 0; rr < 4; rr++) {
            int row  = rq + 4 * rr;
            float gi = sigf(acc[0][rr] + bi);
            float gf = sigf(acc[1][rr] + bf);
            float gg = tanhg(acc[2][rr] + bg);
            float go = sigf(acc[3][rr] + bo);
            float cn = gf * c[rr] + gi * gg;
            c[rr]    = cn;
            float hn = go * tanhg(cn);
            As[row * K + D_IN + u] = hn;
            ouths[(size_t)t * (BB * HH) + (size_t)(rowbase + row) * HH + u] = hn;
        }
        if (t + 1 < TT && tid < 64) {
            int r = tid >> 2, j = tid & 3;
            As[r * K + j] =
                in[(size_t)(rowbase + r) * (TT * D_IN) + (t + 1) * D_IN + j];
        }
        __syncthreads();
    }
}

// ---------------------------------------------------------------------------
// Layers 1-3 recurrence (proven): K = 64; xg prefetched from 4 gate planes.
// ---------------------------------------------------------------------------
__global__ void __launch_bounds__(256, 1)
lstm_recN(const float* __restrict__ xgp, const float* __restrict__ Whh,
          float* __restrict__ ouths, int write_all) {
    constexpr int K = 64, APAD = 68, AW = 17;
    extern __shared__ char sm_raw[];
    float* Ws = (float*)sm_raw;
    float* As = (float*)sm_raw + G4 * APAD;

    const int tid     = threadIdx.x;
    const int u       = tid & 63;
    const int rq      = tid >> 6;
    const int rowbase = blockIdx.x * 16;

    const float* xg_i = xgp;
    const float* xg_f = xgp + PLANE;
    const float* xg_g = xgp + 2 * PLANE;
    const float* xg_o = xgp + 3 * PLANE;

    for (int idx = tid; idx < G4 * K; idx += 256) {
        int g = idx >> 6, k = idx & 63;
        Ws[g * APAD + k] = Whh[idx];
    }
    for (int i = tid; i < 16 * APAD; i += 256) As[i] = 0.0f;
    __syncthreads();

    float c[4] = {0.f, 0.f, 0.f, 0.f};
    const float4* As4 = (const float4*)As;
    const float4* Ws4 = (const float4*)Ws;

    for (int t = 0; t < TT; ++t) {
        float xi[4], xf[4], xgv[4], xo[4];
        #pragma unroll
        for (int rr = 0; rr < 4; rr++) {
            size_t off = ((size_t)t * BB + rowbase + rq + 4 * rr) * HH + u;
            xi[rr]  = xg_i[off];
            xf[rr]  = xg_f[off];
            xgv[rr] = xg_g[off];
            xo[rr]  = xg_o[off];
        }

        float acc[4][4];
        #pragma unroll
        for (int q = 0; q < 4; q++)
            #pragma unroll
            for (int rr = 0; rr < 4; rr++) acc[q][rr] = 0.0f;

        #pragma unroll 4
        for (int k4 = 0; k4 < 16; ++k4) {
            float4 a[4];
            #pragma unroll
            for (int rr = 0; rr < 4; rr++) a[rr] = As4[(rq + 4 * rr) * AW + k4];
            #pragma unroll
            for (int q = 0; q < 4; q++) {
                float4 w = Ws4[(q * 64 + u) * AW + k4];
                #pragma unroll
                for (int rr = 0; rr < 4; rr++) {
                    acc[q][rr] = fmaf(w.x, a[rr].x, acc[q][rr]);
                    acc[q][rr] = fmaf(w.y, a[rr].y, acc[q][rr]);
                    acc[q][rr] = fmaf(w.z, a[rr].z, acc[q][rr]);
                    acc[q][rr] = fmaf(w.w, a[rr].w, acc[q][rr]);
                }
            }
        }
        __syncthreads();

        #pragma unroll
        for (int rr = 0; rr < 4; rr++) {
            int row  = rq + 4 * rr;
            float gi = sigf(acc[0][rr] + xi[rr]);
            float gf = sigf(acc[1][rr] + xf[rr]);
            float gg = tanhg(acc[2][rr] + xgv[rr]);
            float go = sigf(acc[3][rr] + xo[rr]);
            float cn = gf * c[rr] + gi * gg;
            c[rr]    = cn;
            float hn = go * tanhg(cn);
            As[row * APAD + u] = hn;
            if (write_all || t == TT - 1)
                ouths[(size_t)t * (BB * HH) +
                      (size_t)(rowbase + row) * HH + u] = hn;
        }
        __syncthreads();
    }
}

// ---------------------------------------------------------------------------
__global__ void fc_kernel(const float* __restrict__ hs,
                          const float* __restrict__ Wfc,
                          const float* __restrict__ bfc,
                          float* __restrict__ out) {
    int idx = blockIdx.x * blockDim.x + threadIdx.x;
    if (idx >= BB * OUTN) return;
    int b = idx / OUTN, o = idx - b * OUTN;
    const float* h = &hs[(size_t)(TT - 1) * (BB * HH) + (size_t)b * HH];
    float s = bfc[o];
    #pragma unroll
    for (int j = 0; j < HH; j++) s = fmaf(h[j], Wfc[o * HH + j], s);
    out[idx] = s;
}

// ---------------------------------------------------------------------------
extern "C" void kernel_launch(void* const* d_in, const int* in_sizes, int n_in,
                              void* d_out, int out_size) {
    const float* x     = (const float*)d_in[0];
    const float* W_ih0 = (const float*)d_in[1];
    const float* W_ihr = (const float*)d_in[2];
    const float* W_hh  = (const float*)d_in[3];
    const float* b_ih  = (const float*)d_in[4];
    const float* b_hh  = (const float*)d_in[5];
    const float* W_fc  = (const float*)d_in[6];
    const float* b_fc  = (const float*)d_in[7];
    float* out = (float*)d_out;

    float *hsA = nullptr, *hsB = nullptr, *xgp = nullptr;
    float *Whh1 = nullptr, *biasp = nullptr;
    cudaGetSymbolAddress((void**)&hsA, g_hsA);
    cudaGetSymbolAddress((void**)&hsB, g_hsB);
    cudaGetSymbolAddress((void**)&xgp, g_xg);
    cudaGetSymbolAddress((void**)&Whh1, g_Whhsc);
    cudaGetSymbolAddress((void**)&biasp, g_bias);

    constexpr int SMEM_REC = (G4 + 16) * 68 * 4;           // 73,984 B
    constexpr int SMEM_XG  = XG_SMEM_FLOATS * 4;           // 84,992 B
    cudaFuncSetAttribute(lstm_rec0,
                         cudaFuncAttributeMaxDynamicSharedMemorySize, SMEM_REC);
    cudaFuncSetAttribute(lstm_recN,
                         cudaFuncAttributeMaxDynamicSharedMemorySize, SMEM_REC);
    cudaFuncSetAttribute(xg_mma,
                         cudaFuncAttributeMaxDynamicSharedMemorySize, SMEM_XG);

    prep_kernel<<<LL * G4 * 128 / 256, 256>>>(W_ih0, W_hh, b_ih, b_hh);

    lstm_rec0<<<BB / 16, 256, SMEM_REC>>>(x, hsA);

    float* hs_in  = hsA;
    float* hs_out = hsB;
    for (int l = 1; l < LL; ++l) {
        xg_mma<<<XG_GRID, 256, SMEM_XG>>>(
            hs_in, W_ihr + (size_t)(l - 1) * (G4 * HH), biasp + l * G4, xgp);
        lstm_recN<<<BB / 16, 256, SMEM_REC>>>(
            xgp, Whh1 + (size_t)l * (G4 * HH), hs_out, l < LL - 1 ? 1 : 0);
        float* tmp = hs_in; hs_in = hs_out; hs_out = tmp;
    }

    fc_kernel<<<(BB * OUTN + 255) / 256, 256>>>(hs_in, W_fc, b_fc, out);
}

// round 11
// speedup vs baseline: 1.7771x; 1.3950x over previous
#include <cuda_runtime.h>
#include <cstddef>
#include <cstdint>

// Problem constants
#define BB   2048
#define TT   512
#define D_IN 4
#define HH   64
#define LL   4
#define OUTN 5
#define G4   256   // 4*H

#define PLANE ((size_t)TT * BB * HH)   // floats per gate plane

// -------------------------- device scratch --------------------------------
__device__ float g_hsA[(size_t)TT * BB * HH];     // 256 MB ping
__device__ float g_hsB[(size_t)TT * BB * HH];     // 256 MB pong
__device__ float g_xg[4 * PLANE];                 // 1 GB: 4 gate planes [trow][u]
__device__ float g_Whhsc[LL][G4 * HH];            // W_hh scalar [gate][64]
__device__ float g_bias[LL][G4];

__device__ __forceinline__ float sigf(float x) {
    return __fdividef(1.0f, 1.0f + __expf(-x));
}
__device__ __forceinline__ float tanhg(float x) {
    return __fdividef(2.0f, 1.0f + __expf(-2.0f * x)) - 1.0f;
}
__device__ __forceinline__ float tf32_rna(float x) {
    float r;
    asm("cvt.rna.tf32.f32 %0, %1;" : "=f"(r) : "f"(x));
    return r;
}

#define MMA_TF32(c, a, b) \
    asm volatile("mma.sync.aligned.m16n8k8.row.col.f32.tf32.tf32.f32 " \
        "{%0,%1,%2,%3}, {%4,%5,%6,%7}, {%8,%9}, {%0,%1,%2,%3};" \
        : "+f"((c)[0]), "+f"((c)[1]), "+f"((c)[2]), "+f"((c)[3]) \
        : "r"((a)[0]), "r"((a)[1]), "r"((a)[2]), "r"((a)[3]), \
          "r"((b)[0]), "r"((b)[1]))

// ---------------------------------------------------------------------------
// Weight prep: W_hh scalar copy per layer + fused bias.
// ---------------------------------------------------------------------------
__global__ void prep_kernel(const float* __restrict__ W_hh,
                            const float* __restrict__ b_ih,
                            const float* __restrict__ b_hh) {
    int idx = blockIdx.x * blockDim.x + threadIdx.x;   // l*G4*64 + gate*64 + k
    if (idx >= LL * G4 * HH) return;
    int k    = idx & 63;
    int gate = (idx >> 6) & 255;
    int l    = idx >> 14;
    g_Whhsc[l][gate * HH + k] = W_hh[((size_t)l * G4 + gate) * HH + k];
    if (k == 0)
        g_bias[l][gate] = b_ih[l * G4 + gate] + b_hh[l * G4 + gate];
}

// ---------------------------------------------------------------------------
// Layer-0 xg: planes[q][trow][u] = bias + sum_{j<4} x[b][t][j]*W_ih0[q*64+u][j]
//   Memory-bound (1 GB plane write).
// ---------------------------------------------------------------------------
__global__ void __launch_bounds__(256, 4)
xg0_kernel(const float* __restrict__ x, const float* __restrict__ Wih0,
           const float* __restrict__ bias, float* __restrict__ xgp) {
    size_t idx  = (size_t)blockIdx.x * 256 + threadIdx.x;   // trow*64 + u
    size_t trow = idx >> 6;
    int    u    = (int)(idx & 63);
    int    t    = (int)(trow >> 11);          // trow / BB
    int    b    = (int)(trow & 2047);         // trow % BB

    float4 xv = *(const float4*)&x[((size_t)b * TT + t) * D_IN];
    #pragma unroll
    for (int q = 0; q < 4; ++q) {
        int gate = q * 64 + u;
        float4 w = *(const float4*)&Wih0[gate * D_IN];
        float v = bias[gate];
        v = fmaf(xv.x, w.x, v);
        v = fmaf(xv.y, w.y, v);
        v = fmaf(xv.z, w.z, v);
        v = fmaf(xv.w, w.w, v);
        xgp[(size_t)q * PLANE + trow * HH + u] = v;
    }
}

// ====================== mma.sync tf32 xg GEMM (layers 1-3) =================
// Proven R10 kernel: single-pass tf32, 32x64 warp tile, 2 CTAs/SM.
#define XG_GRID   2048
#define XG_TILES  8

#define ASTR 68
#define BSTR 264
#define XA_HI 0
#define XB_HI (XA_HI + 64 * ASTR)            //  4352
#define XG_SMEM_FLOATS (XB_HI + 64 * BSTR)   // 21248 -> 84,992 B

__global__ void __launch_bounds__(256, 2)
xg_mma(const float* __restrict__ hs, const float* __restrict__ Wih,
       const float* __restrict__ bias, float* __restrict__ xgp) {
    extern __shared__ char sm_raw[];
    float* sm = (float*)sm_raw;
    const uint32_t* smu = (const uint32_t*)sm_raw;

    const int tid  = threadIdx.x;
    const int wid  = tid >> 5;
    const int lane = tid & 31;
    const int wm   = wid & 1;
    const int wn   = wid >> 1;
    const int lr   = lane >> 2;
    const int lc   = lane & 3;

    for (int i = tid; i < G4 * HH / 4; i += 256) {
        int n = i >> 4, k = (i & 15) * 4;
        float4 v = *(const float4*)&Wih[n * HH + k];
        sm[XB_HI + (k + 0) * BSTR + n] = tf32_rna(v.x);
        sm[XB_HI + (k + 1) * BSTR + n] = tf32_rna(v.y);
        sm[XB_HI + (k + 2) * BSTR + n] = tf32_rna(v.z);
        sm[XB_HI + (k + 3) * BSTR + n] = tf32_rna(v.w);
    }

    float bias0[8], bias1[8];
    #pragma unroll
    for (int f = 0; f < 8; ++f) {
        int col = wn * 64 + f * 8 + 2 * lc;
        bias0[f] = bias[col];
        bias1[f] = bias[col + 1];
    }

    float* outp = xgp + (size_t)wn * PLANE;

    for (int it = 0; it < XG_TILES; ++it) {
        size_t row0 = ((size_t)it * XG_GRID + blockIdx.x) * 64;

        __syncthreads();
        #pragma unroll
        for (int i = 0; i < 4; ++i) {
            int idx = tid + i * 256;
            int row = idx >> 4, k = (idx & 15) * 4;
            float4 v = *(const float4*)&hs[(row0 + row) * HH + k];
            float4 hi;
            hi.x = tf32_rna(v.x);
            hi.y = tf32_rna(v.y);
            hi.z = tf32_rna(v.z);
            hi.w = tf32_rna(v.w);
            *(float4*)&sm[XA_HI + row * ASTR + k] = hi;
        }
        __syncthreads();

        float c[2][8][4];
        #pragma unroll
        for (int mm = 0; mm < 2; ++mm)
            #pragma unroll
            for (int f = 0; f < 8; ++f) {
                c[mm][f][0] = bias0[f]; c[mm][f][1] = bias1[f];
                c[mm][f][2] = bias0[f]; c[mm][f][3] = bias1[f];
            }

        #pragma unroll
        for (int kc = 0; kc < 8; ++kc) {
            uint32_t a[2][4];
            #pragma unroll
            for (int mm = 0; mm < 2; ++mm) {
                int r = wm * 32 + mm * 16 + lr;
                int k = kc * 8 + lc;
                a[mm][0] = smu[XA_HI + r * ASTR + k];
                a[mm][1] = smu[XA_HI + (r + 8) * ASTR + k];
                a[mm][2] = smu[XA_HI + r * ASTR + k + 4];
                a[mm][3] = smu[XA_HI + (r + 8) * ASTR + k + 4];
            }
            #pragma unroll
            for (int f = 0; f < 8; ++f) {
                int n = wn * 64 + f * 8 + lr;
                int k = kc * 8 + lc;
                uint32_t b[2];
                b[0] = smu[XB_HI + k * BSTR + n];
                b[1] = smu[XB_HI + (k + 4) * BSTR + n];
                MMA_TF32(c[0][f], a[0], b);
                MMA_TF32(c[1][f], a[1], b);
            }
        }

        #pragma unroll
        for (int mm = 0; mm < 2; ++mm) {
            size_t rbase = row0 + wm * 32 + mm * 16 + lr;
            #pragma unroll
            for (int f = 0; f < 8; ++f) {
                int u = f * 8 + 2 * lc;
                *(float2*)&outp[rbase * HH + u] =
                    make_float2(c[mm][f][0], c[mm][f][1]);
                *(float2*)&outp[(rbase + 8) * HH + u] =
                    make_float2(c[mm][f][2], c[mm][f][3]);
            }
        }
    }
}

// ====================== mma.sync recurrence (all layers) ===================
// Per CTA: 16 batch rows x all T. 8 warps; warp w owns u-slice [8w, 8w+8)
// across all 4 gate tiles (n = 64q + 8w). W_hh frags register-resident.
// A = h split hi/lo in SMEM (2-pass tf32; residual = h*W_lo, proven ~1e-4).
// Thread (lr,lc) epilogues cells (row in {lr,lr+8}) x (u in {8w+2lc, +1}).
__global__ void __launch_bounds__(256, 1)
lstm_rec_mma(const float* __restrict__ xgp, const float* __restrict__ Whh,
             float* __restrict__ ouths, int write_all) {
    __shared__ float Ah[16 * ASTR];
    __shared__ float Al[16 * ASTR];

    const int tid  = threadIdx.x;
    const int wid  = tid >> 5;
    const int lane = tid & 31;
    const int lr   = lane >> 2;
    const int lc   = lane & 3;
    const int rowbase = blockIdx.x * 16;

    const float* xg_pl[4] = {xgp, xgp + PLANE, xgp + 2 * PLANE, xgp + 3 * PLANE};

    // W_hh fragments -> registers (64 regs)
    uint32_t bfr[4][8][2];
    #pragma unroll
    for (int q = 0; q < 4; ++q) {
        int n = q * 64 + wid * 8 + lr;
        #pragma unroll
        for (int kc = 0; kc < 8; ++kc) {
            bfr[q][kc][0] = __float_as_uint(tf32_rna(Whh[n * HH + kc * 8 + lc]));
            bfr[q][kc][1] = __float_as_uint(tf32_rna(Whh[n * HH + kc * 8 + lc + 4]));
        }
    }

    // h = 0 initial state
    for (int i = tid; i < 16 * ASTR; i += 256) { Ah[i] = 0.0f; Al[i] = 0.0f; }
    __syncthreads();

    float cst[4] = {0.f, 0.f, 0.f, 0.f};
    const int u0 = wid * 8 + 2 * lc;

    for (int t = 0; t < TT; ++t) {
        // ---- prefetch xg gate values for this thread's 4 cells ----
        float2 xv[4][2];
        #pragma unroll
        for (int q = 0; q < 4; ++q) {
            #pragma unroll
            for (int rr = 0; rr < 2; ++rr) {
                size_t trow = (size_t)t * BB + rowbase + lr + 8 * rr;
                xv[q][rr] = __ldg((const float2*)&xg_pl[q][trow * HH + u0]);
            }
        }

        // ---- GEMM: acc[q] = h . W_hh^T (2-pass tf32: A_hi + A_lo) ----
        float acc[4][4];
        #pragma unroll
        for (int q = 0; q < 4; ++q) {
            acc[q][0] = 0.f; acc[q][1] = 0.f; acc[q][2] = 0.f; acc[q][3] = 0.f;
        }

        #pragma unroll
        for (int kc = 0; kc < 8; ++kc) {
            int k = kc * 8 + lc;
            uint32_t a[4];
            a[0] = *(const uint32_t*)&Ah[lr * ASTR + k];
            a[1] = *(const uint32_t*)&Ah[(lr + 8) * ASTR + k];
            a[2] = *(const uint32_t*)&Ah[lr * ASTR + k + 4];
            a[3] = *(const uint32_t*)&Ah[(lr + 8) * ASTR + k + 4];
            MMA_TF32(acc[0], a, bfr[0][kc]);
            MMA_TF32(acc[1], a, bfr[1][kc]);
            MMA_TF32(acc[2], a, bfr[2][kc]);
            MMA_TF32(acc[3], a, bfr[3][kc]);
            a[0] = *(const uint32_t*)&Al[lr * ASTR + k];
            a[1] = *(const uint32_t*)&Al[(lr + 8) * ASTR + k];
            a[2] = *(const uint32_t*)&Al[lr * ASTR + k + 4];
            a[3] = *(const uint32_t*)&Al[(lr + 8) * ASTR + k + 4];
            MMA_TF32(acc[0], a, bfr[0][kc]);
            MMA_TF32(acc[1], a, bfr[1][kc]);
            MMA_TF32(acc[2], a, bfr[2][kc]);
            MMA_TF32(acc[3], a, bfr[3][kc]);
        }
        __syncthreads();   // all A reads done before h overwrite

        // ---- epilogue: 2 rows x 2 units, thread-local ----
        #pragma unroll
        for (int rr = 0; rr < 2; ++rr) {
            int row = lr + 8 * rr;
            int j0  = rr * 2;
            float gi0 = sigf(acc[0][j0]     + xv[0][rr].x);
            float gf0 = sigf(acc[1][j0]     + xv[1][rr].x);
            float gg0 = tanhg(acc[2][j0]    + xv[2][rr].x);
            float go0 = sigf(acc[3][j0]     + xv[3][rr].x);
            float gi1 = sigf(acc[0][j0 + 1] + xv[0][rr].y);
            float gf1 = sigf(acc[1][j0 + 1] + xv[1][rr].y);
            float gg1 = tanhg(acc[2][j0 + 1] + xv[2][rr].y);
            float go1 = sigf(acc[3][j0 + 1] + xv[3][rr].y);

            float cn0 = gf0 * cst[j0]     + gi0 * gg0;
            float cn1 = gf1 * cst[j0 + 1] + gi1 * gg1;
            cst[j0]     = cn0;
            cst[j0 + 1] = cn1;
            float hn0 = go0 * tanhg(cn0);
            float hn1 = go1 * tanhg(cn1);

            float h0hi = tf32_rna(hn0), h1hi = tf32_rna(hn1);
            *(float2*)&Ah[row * ASTR + u0] = make_float2(h0hi, h1hi);
            *(float2*)&Al[row * ASTR + u0] =
                make_float2(tf32_rna(hn0 - h0hi), tf32_rna(hn1 - h1hi));

            if (write_all || t == TT - 1) {
                size_t trow = (size_t)t * BB + rowbase + row;
                *(float2*)&ouths[trow * HH + u0] = make_float2(hn0, hn1);
            }
        }
        __syncthreads();   // h visible before next step's MMA reads
    }
}

// ---------------------------------------------------------------------------
__global__ void fc_kernel(const float* __restrict__ hs,
                          const float* __restrict__ Wfc,
                          const float* __restrict__ bfc,
                          float* __restrict__ out) {
    int idx = blockIdx.x * blockDim.x + threadIdx.x;
    if (idx >= BB * OUTN) return;
    int b = idx / OUTN, o = idx - b * OUTN;
    const float* h = &hs[(size_t)(TT - 1) * (BB * HH) + (size_t)b * HH];
    float s = bfc[o];
    #pragma unroll
    for (int j = 0; j < HH; j++) s = fmaf(h[j], Wfc[o * HH + j], s);
    out[idx] = s;
}

// ---------------------------------------------------------------------------
extern "C" void kernel_launch(void* const* d_in, const int* in_sizes, int n_in,
                              void* d_out, int out_size) {
    const float* x     = (const float*)d_in[0];
    const float* W_ih0 = (const float*)d_in[1];
    const float* W_ihr = (const float*)d_in[2];
    const float* W_hh  = (const float*)d_in[3];
    const float* b_ih  = (const float*)d_in[4];
    const float* b_hh  = (const float*)d_in[5];
    const float* W_fc  = (const float*)d_in[6];
    const float* b_fc  = (const float*)d_in[7];
    float* out = (float*)d_out;

    float *hsA = nullptr, *hsB = nullptr, *xgp = nullptr;
    float *Whh1 = nullptr, *biasp = nullptr;
    cudaGetSymbolAddress((void**)&hsA, g_hsA);
    cudaGetSymbolAddress((void**)&hsB, g_hsB);
    cudaGetSymbolAddress((void**)&xgp, g_xg);
    cudaGetSymbolAddress((void**)&Whh1, g_Whhsc);
    cudaGetSymbolAddress((void**)&biasp, g_bias);

    constexpr int SMEM_XG = XG_SMEM_FLOATS * 4;   // 84,992 B
    cudaFuncSetAttribute(xg_mma,
                         cudaFuncAttributeMaxDynamicSharedMemorySize, SMEM_XG);

    prep_kernel<<<LL * G4 * HH / 256, 256>>>(W_hh, b_ih, b_hh);

    // Layer 0: cheap input-GEMM planes + mma recurrence
    xg0_kernel<<<(int)((PLANE) / 256), 256>>>(x, W_ih0, biasp, xgp);
    lstm_rec_mma<<<BB / 16, 256>>>(xgp, Whh1, hsA, 1);

    float* hs_in  = hsA;
    float* hs_out = hsB;
    for (int l = 1; l < LL; ++l) {
        xg_mma<<<XG_GRID, 256, SMEM_XG>>>(
            hs_in, W_ihr + (size_t)(l - 1) * (G4 * HH), biasp + l * G4, xgp);
        lstm_rec_mma<<<BB / 16, 256>>>(
            xgp, Whh1 + (size_t)l * (G4 * HH), hs_out, l < LL - 1 ? 1 : 0);
        float* tmp = hs_in; hs_in = hs_out; hs_out = tmp;
    }

    fc_kernel<<<(BB * OUTN + 255) / 256, 256>>>(hs_in, W_fc, b_fc, out);
}

// round 12
// speedup vs baseline: 1.9204x; 1.0806x over previous
#include <cuda_runtime.h>
#include <cstddef>
#include <cstdint>

// Problem constants
#define BB   2048
#define TT   512
#define D_IN 4
#define HH   64
#define LL   4
#define OUTN 5
#define G4   256   // 4*H

#define PLANE ((size_t)TT * BB * HH)   // floats per gate plane

// -------------------------- device scratch --------------------------------
__device__ float g_hsA[(size_t)TT * BB * HH];     // 256 MB ping
__device__ float g_hsB[(size_t)TT * BB * HH];     // 256 MB pong
__device__ float g_xg[4 * PLANE];                 // 1 GB: 4 gate planes [trow][u]
__device__ float g_Whhsc[LL][G4 * HH];            // W_hh scalar [gate][64]
__device__ float g_bias[LL][G4];

__device__ __forceinline__ float sigf(float x) {
    return __fdividef(1.0f, 1.0f + __expf(-x));
}
__device__ __forceinline__ float tanhg(float x) {
    return __fdividef(2.0f, 1.0f + __expf(-2.0f * x)) - 1.0f;
}
__device__ __forceinline__ float tf32_rna(float x) {
    float r;
    asm("cvt.rna.tf32.f32 %0, %1;" : "=f"(r) : "f"(x));
    return r;
}

#define MMA_TF32(c, a, b) \
    asm volatile("mma.sync.aligned.m16n8k8.row.col.f32.tf32.tf32.f32 " \
        "{%0,%1,%2,%3}, {%4,%5,%6,%7}, {%8,%9}, {%0,%1,%2,%3};" \
        : "+f"((c)[0]), "+f"((c)[1]), "+f"((c)[2]), "+f"((c)[3]) \
        : "r"((a)[0]), "r"((a)[1]), "r"((a)[2]), "r"((a)[3]), \
          "r"((b)[0]), "r"((b)[1]))

// ---------------------------------------------------------------------------
// Weight prep: W_hh scalar copy per layer + fused bias.
// ---------------------------------------------------------------------------
__global__ void prep_kernel(const float* __restrict__ W_hh,
                            const float* __restrict__ b_ih,
                            const float* __restrict__ b_hh) {
    int idx = blockIdx.x * blockDim.x + threadIdx.x;
    if (idx >= LL * G4 * HH) return;
    int k    = idx & 63;
    int gate = (idx >> 6) & 255;
    int l    = idx >> 14;
    g_Whhsc[l][gate * HH + k] = W_hh[((size_t)l * G4 + gate) * HH + k];
    if (k == 0)
        g_bias[l][gate] = b_ih[l * G4 + gate] + b_hh[l * G4 + gate];
}

// ---------------------------------------------------------------------------
// Layer-0 xg: memory-bound plane fill.
// ---------------------------------------------------------------------------
__global__ void __launch_bounds__(256, 4)
xg0_kernel(const float* __restrict__ x, const float* __restrict__ Wih0,
           const float* __restrict__ bias, float* __restrict__ xgp) {
    size_t idx  = (size_t)blockIdx.x * 256 + threadIdx.x;
    size_t trow = idx >> 6;
    int    u    = (int)(idx & 63);
    int    t    = (int)(trow >> 11);
    int    b    = (int)(trow & 2047);

    float4 xv = *(const float4*)&x[((size_t)b * TT + t) * D_IN];
    #pragma unroll
    for (int q = 0; q < 4; ++q) {
        int gate = q * 64 + u;
        float4 w = *(const float4*)&Wih0[gate * D_IN];
        float v = bias[gate];
        v = fmaf(xv.x, w.x, v);
        v = fmaf(xv.y, w.y, v);
        v = fmaf(xv.z, w.z, v);
        v = fmaf(xv.w, w.w, v);
        xgp[(size_t)q * PLANE + trow * HH + u] = v;
    }
}

// ====================== mma.sync tf32 xg GEMM (layers 1-3) =================
#define XG_GRID   2048
#define XG_TILES  8

#define ASTR 68
#define BSTR 264
#define XA_HI 0
#define XB_HI (XA_HI + 64 * ASTR)
#define XG_SMEM_FLOATS (XB_HI + 64 * BSTR)   // 21248 -> 84,992 B

__global__ void __launch_bounds__(256, 2)
xg_mma(const float* __restrict__ hs, const float* __restrict__ Wih,
       const float* __restrict__ bias, float* __restrict__ xgp) {
    extern __shared__ char sm_raw[];
    float* sm = (float*)sm_raw;
    const uint32_t* smu = (const uint32_t*)sm_raw;

    const int tid  = threadIdx.x;
    const int wid  = tid >> 5;
    const int lane = tid & 31;
    const int wm   = wid & 1;
    const int wn   = wid >> 1;
    const int lr   = lane >> 2;
    const int lc   = lane & 3;

    for (int i = tid; i < G4 * HH / 4; i += 256) {
        int n = i >> 4, k = (i & 15) * 4;
        float4 v = *(const float4*)&Wih[n * HH + k];
        sm[XB_HI + (k + 0) * BSTR + n] = tf32_rna(v.x);
        sm[XB_HI + (k + 1) * BSTR + n] = tf32_rna(v.y);
        sm[XB_HI + (k + 2) * BSTR + n] = tf32_rna(v.z);
        sm[XB_HI + (k + 3) * BSTR + n] = tf32_rna(v.w);
    }

    float bias0[8], bias1[8];
    #pragma unroll
    for (int f = 0; f < 8; ++f) {
        int col = wn * 64 + f * 8 + 2 * lc;
        bias0[f] = bias[col];
        bias1[f] = bias[col + 1];
    }

    float* outp = xgp + (size_t)wn * PLANE;

    for (int it = 0; it < XG_TILES; ++it) {
        size_t row0 = ((size_t)it * XG_GRID + blockIdx.x) * 64;

        __syncthreads();
        #pragma unroll
        for (int i = 0; i < 4; ++i) {
            int idx = tid + i * 256;
            int row = idx >> 4, k = (idx & 15) * 4;
            float4 v = *(const float4*)&hs[(row0 + row) * HH + k];
            float4 hi;
            hi.x = tf32_rna(v.x);
            hi.y = tf32_rna(v.y);
            hi.z = tf32_rna(v.z);
            hi.w = tf32_rna(v.w);
            *(float4*)&sm[XA_HI + row * ASTR + k] = hi;
        }
        __syncthreads();

        float c[2][8][4];
        #pragma unroll
        for (int mm = 0; mm < 2; ++mm)
            #pragma unroll
            for (int f = 0; f < 8; ++f) {
                c[mm][f][0] = bias0[f]; c[mm][f][1] = bias1[f];
                c[mm][f][2] = bias0[f]; c[mm][f][3] = bias1[f];
            }

        #pragma unroll
        for (int kc = 0; kc < 8; ++kc) {
            uint32_t a[2][4];
            #pragma unroll
            for (int mm = 0; mm < 2; ++mm) {
                int r = wm * 32 + mm * 16 + lr;
                int k = kc * 8 + lc;
                a[mm][0] = smu[XA_HI + r * ASTR + k];
                a[mm][1] = smu[XA_HI + (r + 8) * ASTR + k];
                a[mm][2] = smu[XA_HI + r * ASTR + k + 4];
                a[mm][3] = smu[XA_HI + (r + 8) * ASTR + k + 4];
            }
            #pragma unroll
            for (int f = 0; f < 8; ++f) {
                int n = wn * 64 + f * 8 + lr;
                int k = kc * 8 + lc;
                uint32_t b[2];
                b[0] = smu[XB_HI + k * BSTR + n];
                b[1] = smu[XB_HI + (k + 4) * BSTR + n];
                MMA_TF32(c[0][f], a[0], b);
                MMA_TF32(c[1][f], a[1], b);
            }
        }

        #pragma unroll
        for (int mm = 0; mm < 2; ++mm) {
            size_t rbase = row0 + wm * 32 + mm * 16 + lr;
            #pragma unroll
            for (int f = 0; f < 8; ++f) {
                int u = f * 8 + 2 * lc;
                *(float2*)&outp[rbase * HH + u] =
                    make_float2(c[mm][f][0], c[mm][f][1]);
                *(float2*)&outp[(rbase + 8) * HH + u] =
                    make_float2(c[mm][f][2], c[mm][f][3]);
            }
        }
    }
}

// ====================== mma.sync recurrence (all layers) ===================
// Single-pass tf32 (h quantized to tf32 at feedback), W_hh frags in regs.
// Double-buffered h -> ONE __syncthreads per step.
__global__ void __launch_bounds__(256, 1)
lstm_rec_mma(const float* __restrict__ xgp, const float* __restrict__ Whh,
             float* __restrict__ ouths, int write_all) {
    __shared__ float Ah[2][16 * ASTR];

    const int tid  = threadIdx.x;
    const int wid  = tid >> 5;
    const int lane = tid & 31;
    const int lr   = lane >> 2;
    const int lc   = lane & 3;
    const int rowbase = blockIdx.x * 16;

    const float* xg_pl[4] = {xgp, xgp + PLANE, xgp + 2 * PLANE, xgp + 3 * PLANE};

    // W_hh fragments -> registers (64 regs)
    uint32_t bfr[4][8][2];
    #pragma unroll
    for (int q = 0; q < 4; ++q) {
        int n = q * 64 + wid * 8 + lr;
        #pragma unroll
        for (int kc = 0; kc < 8; ++kc) {
            bfr[q][kc][0] = __float_as_uint(tf32_rna(Whh[n * HH + kc * 8 + lc]));
            bfr[q][kc][1] = __float_as_uint(tf32_rna(Whh[n * HH + kc * 8 + lc + 4]));
        }
    }

    // h = 0 initial state (both buffers)
    for (int i = tid; i < 2 * 16 * ASTR; i += 256)
        Ah[0][i] = 0.0f;   // contiguous union of both buffers
    __syncthreads();

    float cst[4] = {0.f, 0.f, 0.f, 0.f};
    const int u0 = wid * 8 + 2 * lc;

    for (int t = 0; t < TT; ++t) {
        const float* Ard = Ah[t & 1];
        float*       Awr = Ah[(t + 1) & 1];

        // ---- prefetch xg gate values ----
        float2 xv[4][2];
        #pragma unroll
        for (int q = 0; q < 4; ++q) {
            #pragma unroll
            for (int rr = 0; rr < 2; ++rr) {
                size_t trow = (size_t)t * BB + rowbase + lr + 8 * rr;
                xv[q][rr] = __ldg((const float2*)&xg_pl[q][trow * HH + u0]);
            }
        }

        // ---- GEMM: acc[q] = h . W_hh^T (single-pass tf32) ----
        float acc[4][4];
        #pragma unroll
        for (int q = 0; q < 4; ++q) {
            acc[q][0] = 0.f; acc[q][1] = 0.f; acc[q][2] = 0.f; acc[q][3] = 0.f;
        }

        #pragma unroll
        for (int kc = 0; kc < 8; ++kc) {
            int k = kc * 8 + lc;
            uint32_t a[4];
            a[0] = *(const uint32_t*)&Ard[lr * ASTR + k];
            a[1] = *(const uint32_t*)&Ard[(lr + 8) * ASTR + k];
            a[2] = *(const uint32_t*)&Ard[lr * ASTR + k + 4];
            a[3] = *(const uint32_t*)&Ard[(lr + 8) * ASTR + k + 4];
            MMA_TF32(acc[0], a, bfr[0][kc]);
            MMA_TF32(acc[1], a, bfr[1][kc]);
            MMA_TF32(acc[2], a, bfr[2][kc]);
            MMA_TF32(acc[3], a, bfr[3][kc]);
        }

        // ---- epilogue: 2 rows x 2 units, thread-local; write OTHER buffer ----
        #pragma unroll
        for (int rr = 0; rr < 2; ++rr) {
            int row = lr + 8 * rr;
            int j0  = rr * 2;
            float gi0 = sigf(acc[0][j0]      + xv[0][rr].x);
            float gf0 = sigf(acc[1][j0]      + xv[1][rr].x);
            float gg0 = tanhg(acc[2][j0]     + xv[2][rr].x);
            float go0 = sigf(acc[3][j0]      + xv[3][rr].x);
            float gi1 = sigf(acc[0][j0 + 1]  + xv[0][rr].y);
            float gf1 = sigf(acc[1][j0 + 1]  + xv[1][rr].y);
            float gg1 = tanhg(acc[2][j0 + 1] + xv[2][rr].y);
            float go1 = sigf(acc[3][j0 + 1]  + xv[3][rr].y);

            float cn0 = gf0 * cst[j0]     + gi0 * gg0;
            float cn1 = gf1 * cst[j0 + 1] + gi1 * gg1;
            cst[j0]     = cn0;
            cst[j0 + 1] = cn1;
            float hn0 = go0 * tanhg(cn0);
            float hn1 = go1 * tanhg(cn1);

            *(float2*)&Awr[row * ASTR + u0] =
                make_float2(tf32_rna(hn0), tf32_rna(hn1));

            if (write_all || t == TT - 1) {
                size_t trow = (size_t)t * BB + rowbase + row;
                *(float2*)&ouths[trow * HH + u0] = make_float2(hn0, hn1);
            }
        }
        __syncthreads();   // h(t+1) visible; old buffer free for next write
    }
}

// ---------------------------------------------------------------------------
__global__ void fc_kernel(const float* __restrict__ hs,
                          const float* __restrict__ Wfc,
                          const float* __restrict__ bfc,
                          float* __restrict__ out) {
    int idx = blockIdx.x * blockDim.x + threadIdx.x;
    if (idx >= BB * OUTN) return;
    int b = idx / OUTN, o = idx - b * OUTN;
    const float* h = &hs[(size_t)(TT - 1) * (BB * HH) + (size_t)b * HH];
    float s = bfc[o];
    #pragma unroll
    for (int j = 0; j < HH; j++) s = fmaf(h[j], Wfc[o * HH + j], s);
    out[idx] = s;
}

// ---------------------------------------------------------------------------
extern "C" void kernel_launch(void* const* d_in, const int* in_sizes, int n_in,
                              void* d_out, int out_size) {
    const float* x     = (const float*)d_in[0];
    const float* W_ih0 = (const float*)d_in[1];
    const float* W_ihr = (const float*)d_in[2];
    const float* W_hh  = (const float*)d_in[3];
    const float* b_ih  = (const float*)d_in[4];
    const float* b_hh  = (const float*)d_in[5];
    const float* W_fc  = (const float*)d_in[6];
    const float* b_fc  = (const float*)d_in[7];
    float* out = (float*)d_out;

    float *hsA = nullptr, *hsB = nullptr, *xgp = nullptr;
    float *Whh1 = nullptr, *biasp = nullptr;
    cudaGetSymbolAddress((void**)&hsA, g_hsA);
    cudaGetSymbolAddress((void**)&hsB, g_hsB);
    cudaGetSymbolAddress((void**)&xgp, g_xg);
    cudaGetSymbolAddress((void**)&Whh1, g_Whhsc);
    cudaGetSymbolAddress((void**)&biasp, g_bias);

    constexpr int SMEM_XG = XG_SMEM_FLOATS * 4;   // 84,992 B
    cudaFuncSetAttribute(xg_mma,
                         cudaFuncAttributeMaxDynamicSharedMemorySize, SMEM_XG);

    prep_kernel<<<LL * G4 * HH / 256, 256>>>(W_hh, b_ih, b_hh);

    // Layer 0
    xg0_kernel<<<(int)(PLANE / 256), 256>>>(x, W_ih0, biasp, xgp);
    lstm_rec_mma<<<BB / 16, 256>>>(xgp, Whh1, hsA, 1);

    float* hs_in  = hsA;
    float* hs_out = hsB;
    for (int l = 1; l < LL; ++l) {
        xg_mma<<<XG_GRID, 256, SMEM_XG>>>(
            hs_in, W_ihr + (size_t)(l - 1) * (G4 * HH), biasp + l * G4, xgp);
        lstm_rec_mma<<<BB / 16, 256>>>(
            xgp, Whh1 + (size_t)l * (G4 * HH), hs_out, l < LL - 1 ? 1 : 0);
        float* tmp = hs_in; hs_in = hs_out; hs_out = tmp;
    }

    fc_kernel<<<(BB * OUTN + 255) / 256, 256>>>(hs_in, W_fc, b_fc, out);
}

// round 13
// speedup vs baseline: 2.6832x; 1.3972x over previous
#include <cuda_runtime.h>
#include <cstddef>
#include <cstdint>

// Problem constants
#define BB   2048
#define TT   512
#define D_IN 4
#define HH   64
#define LL   4
#define OUTN 5
#define G4   256   // 4*H

#define PLANE ((size_t)TT * BB * HH)   // floats per gate plane

// -------------------------- device scratch --------------------------------
__device__ float g_hsA[(size_t)TT * BB * HH];     // 256 MB ping
__device__ float g_hsB[(size_t)TT * BB * HH];     // 256 MB pong
__device__ float g_xg[4 * PLANE];                 // 1 GB: layer-0 gate planes
__device__ float g_bias[LL][G4];

__device__ __forceinline__ float sigf(float x) {
    return __fdividef(1.0f, 1.0f + __expf(-x));
}
__device__ __forceinline__ float tanhg(float x) {
    return __fdividef(2.0f, 1.0f + __expf(-2.0f * x)) - 1.0f;
}
__device__ __forceinline__ float tf32_rna(float x) {
    float r;
    asm("cvt.rna.tf32.f32 %0, %1;" : "=f"(r) : "f"(x));
    return r;
}

#define MMA_TF32(c, a, b) \
    asm volatile("mma.sync.aligned.m16n8k8.row.col.f32.tf32.tf32.f32 " \
        "{%0,%1,%2,%3}, {%4,%5,%6,%7}, {%8,%9}, {%0,%1,%2,%3};" \
        : "+f"((c)[0]), "+f"((c)[1]), "+f"((c)[2]), "+f"((c)[3]) \
        : "r"((a)[0]), "r"((a)[1]), "r"((a)[2]), "r"((a)[3]), \
          "r"((b)[0]), "r"((b)[1]))

#define ASTR 68

// ---------------------------------------------------------------------------
// Weight prep: fused bias only.
// ---------------------------------------------------------------------------
__global__ void prep_kernel(const float* __restrict__ b_ih,
                            const float* __restrict__ b_hh) {
    int idx = blockIdx.x * blockDim.x + threadIdx.x;
    if (idx >= LL * G4) return;
    g_bias[idx >> 8][idx & 255] = b_ih[idx] + b_hh[idx];
}

// ---------------------------------------------------------------------------
// Layer-0 xg: memory-bound plane fill (K=4 input GEMM).
// ---------------------------------------------------------------------------
__global__ void __launch_bounds__(256, 4)
xg0_kernel(const float* __restrict__ x, const float* __restrict__ Wih0,
           const float* __restrict__ bias, float* __restrict__ xgp) {
    size_t idx  = (size_t)blockIdx.x * 256 + threadIdx.x;
    size_t trow = idx >> 6;
    int    u    = (int)(idx & 63);
    int    t    = (int)(trow >> 11);
    int    b    = (int)(trow & 2047);

    float4 xv = *(const float4*)&x[((size_t)b * TT + t) * D_IN];
    #pragma unroll
    for (int q = 0; q < 4; ++q) {
        int gate = q * 64 + u;
        float4 w = *(const float4*)&Wih0[gate * D_IN];
        float v = bias[gate];
        v = fmaf(xv.x, w.x, v);
        v = fmaf(xv.y, w.y, v);
        v = fmaf(xv.z, w.z, v);
        v = fmaf(xv.w, w.w, v);
        xgp[(size_t)q * PLANE + trow * HH + u] = v;
    }
}

// ====================== layer-0 recurrence (xg planes) =====================
// Proven R12 kernel: single-pass tf32, W_hh frags in regs, double-buffered h.
__global__ void __launch_bounds__(256, 1)
lstm_rec_mma(const float* __restrict__ xgp, const float* __restrict__ Whh,
             float* __restrict__ ouths, int write_all) {
    __shared__ float Ah[2][16 * ASTR];

    const int tid  = threadIdx.x;
    const int wid  = tid >> 5;
    const int lane = tid & 31;
    const int lr   = lane >> 2;
    const int lc   = lane & 3;
    const int rowbase = blockIdx.x * 16;

    const float* xg_pl[4] = {xgp, xgp + PLANE, xgp + 2 * PLANE, xgp + 3 * PLANE};

    uint32_t bfr[4][8][2];
    #pragma unroll
    for (int q = 0; q < 4; ++q) {
        int n = q * 64 + wid * 8 + lr;
        #pragma unroll
        for (int kc = 0; kc < 8; ++kc) {
            bfr[q][kc][0] = __float_as_uint(tf32_rna(Whh[n * HH + kc * 8 + lc]));
            bfr[q][kc][1] = __float_as_uint(tf32_rna(Whh[n * HH + kc * 8 + lc + 4]));
        }
    }

    for (int i = tid; i < 2 * 16 * ASTR; i += 256) Ah[0][i] = 0.0f;
    __syncthreads();

    float cst[4] = {0.f, 0.f, 0.f, 0.f};
    const int u0 = wid * 8 + 2 * lc;

    for (int t = 0; t < TT; ++t) {
        const float* Ard = Ah[t & 1];
        float*       Awr = Ah[(t + 1) & 1];

        float2 xv[4][2];
        #pragma unroll
        for (int q = 0; q < 4; ++q)
            #pragma unroll
            for (int rr = 0; rr < 2; ++rr) {
                size_t trow = (size_t)t * BB + rowbase + lr + 8 * rr;
                xv[q][rr] = __ldg((const float2*)&xg_pl[q][trow * HH + u0]);
            }

        float acc[4][4];
        #pragma unroll
        for (int q = 0; q < 4; ++q) {
            acc[q][0] = 0.f; acc[q][1] = 0.f; acc[q][2] = 0.f; acc[q][3] = 0.f;
        }

        #pragma unroll
        for (int kc = 0; kc < 8; ++kc) {
            int k = kc * 8 + lc;
            uint32_t a[4];
            a[0] = *(const uint32_t*)&Ard[lr * ASTR + k];
            a[1] = *(const uint32_t*)&Ard[(lr + 8) * ASTR + k];
            a[2] = *(const uint32_t*)&Ard[lr * ASTR + k + 4];
            a[3] = *(const uint32_t*)&Ard[(lr + 8) * ASTR + k + 4];
            MMA_TF32(acc[0], a, bfr[0][kc]);
            MMA_TF32(acc[1], a, bfr[1][kc]);
            MMA_TF32(acc[2], a, bfr[2][kc]);
            MMA_TF32(acc[3], a, bfr[3][kc]);
        }

        #pragma unroll
        for (int rr = 0; rr < 2; ++rr) {
            int row = lr + 8 * rr;
            int j0  = rr * 2;
            float gi0 = sigf(acc[0][j0]      + xv[0][rr].x);
            float gf0 = sigf(acc[1][j0]      + xv[1][rr].x);
            float gg0 = tanhg(acc[2][j0]     + xv[2][rr].x);
            float go0 = sigf(acc[3][j0]      + xv[3][rr].x);
            float gi1 = sigf(acc[0][j0 + 1]  + xv[0][rr].y);
            float gf1 = sigf(acc[1][j0 + 1]  + xv[1][rr].y);
            float gg1 = tanhg(acc[2][j0 + 1] + xv[2][rr].y);
            float go1 = sigf(acc[3][j0 + 1]  + xv[3][rr].y);

            float cn0 = gf0 * cst[j0]     + gi0 * gg0;
            float cn1 = gf1 * cst[j0 + 1] + gi1 * gg1;
            cst[j0]     = cn0;
            cst[j0 + 1] = cn1;
            float hn0 = go0 * tanhg(cn0);
            float hn1 = go1 * tanhg(cn1);

            *(float2*)&Awr[row * ASTR + u0] =
                make_float2(tf32_rna(hn0), tf32_rna(hn1));

            if (write_all || t == TT - 1) {
                size_t trow = (size_t)t * BB + rowbase + row;
                *(float2*)&ouths[trow * HH + u0] = make_float2(hn0, hn1);
            }
        }
        __syncthreads();
    }
}

// ====================== fused recurrence (layers 1-3) ======================
// Computes x.W_ih AND h.W_hh in one MMA chain per step.
//   A = [x_t | h_t] as two 16x64 SMEM tiles (both double-buffered).
//   W_ih, W_hh frags register-resident (128 regs). x(t+1) prefetched from
//   hs_prev under step t's MMAs. Bias folded into accumulator init.
__global__ void __launch_bounds__(256, 1)
lstm_rec_fused(const float* __restrict__ hs_prev, const float* __restrict__ Wih,
               const float* __restrict__ Whh, const float* __restrict__ bias,
               float* __restrict__ ouths, int write_all) {
    __shared__ float Ax[2][16 * ASTR];
    __shared__ float Ah[2][16 * ASTR];

    const int tid  = threadIdx.x;
    const int wid  = tid >> 5;
    const int lane = tid & 31;
    const int lr   = lane >> 2;
    const int lc   = lane & 3;
    const int rowbase = blockIdx.x * 16;

    // Weight fragments -> registers (128 regs)
    uint32_t bfi[4][8][2], bfh[4][8][2];
    #pragma unroll
    for (int q = 0; q < 4; ++q) {
        int n = q * 64 + wid * 8 + lr;
        #pragma unroll
        for (int kc = 0; kc < 8; ++kc) {
            bfi[q][kc][0] = __float_as_uint(tf32_rna(Wih[n * HH + kc * 8 + lc]));
            bfi[q][kc][1] = __float_as_uint(tf32_rna(Wih[n * HH + kc * 8 + lc + 4]));
            bfh[q][kc][0] = __float_as_uint(tf32_rna(Whh[n * HH + kc * 8 + lc]));
            bfh[q][kc][1] = __float_as_uint(tf32_rna(Whh[n * HH + kc * 8 + lc + 4]));
        }
    }

    const int u0 = wid * 8 + 2 * lc;
    float2 bias_r[4];
    #pragma unroll
    for (int q = 0; q < 4; ++q)
        bias_r[q] = *(const float2*)&bias[q * 64 + u0];

    // h = 0; stage x(0)
    for (int i = tid; i < 2 * 16 * ASTR; i += 256) Ah[0][i] = 0.0f;
    {
        int row = tid >> 4, kk = (tid & 15) * 4;
        float4 v = *(const float4*)&hs_prev[(size_t)(rowbase + row) * HH + kk];
        Ax[0][row * ASTR + kk + 0] = tf32_rna(v.x);
        Ax[0][row * ASTR + kk + 1] = tf32_rna(v.y);
        Ax[0][row * ASTR + kk + 2] = tf32_rna(v.z);
        Ax[0][row * ASTR + kk + 3] = tf32_rna(v.w);
    }
    __syncthreads();

    float cst[4] = {0.f, 0.f, 0.f, 0.f};
    const int xrow = tid >> 4;
    const int xkk  = (tid & 15) * 4;

    for (int t = 0; t < TT; ++t) {
        const float* Axr = Ax[t & 1];
        const float* Ahr = Ah[t & 1];
        float*       Axw = Ax[(t + 1) & 1];
        float*       Ahw = Ah[(t + 1) & 1];

        // ---- prefetch x(t+1) (LDG issues early; hidden under MMAs) ----
        float4 xnext;
        if (t + 1 < TT)
            xnext = *(const float4*)&hs_prev[((size_t)(t + 1) * BB +
                                              rowbase + xrow) * HH + xkk];

        // ---- MMA: acc[q] = bias + x.W_ih^T + h.W_hh^T ----
        float acc[4][4];
        #pragma unroll
        for (int q = 0; q < 4; ++q) {
            acc[q][0] = bias_r[q].x; acc[q][1] = bias_r[q].y;
            acc[q][2] = bias_r[q].x; acc[q][3] = bias_r[q].y;
        }

        #pragma unroll
        for (int kc = 0; kc < 8; ++kc) {
            int k = kc * 8 + lc;
            uint32_t a[4];
            a[0] = *(const uint32_t*)&Axr[lr * ASTR + k];
            a[1] = *(const uint32_t*)&Axr[(lr + 8) * ASTR + k];
            a[2] = *(const uint32_t*)&Axr[lr * ASTR + k + 4];
            a[3] = *(const uint32_t*)&Axr[(lr + 8) * ASTR + k + 4];
            MMA_TF32(acc[0], a, bfi[0][kc]);
            MMA_TF32(acc[1], a, bfi[1][kc]);
            MMA_TF32(acc[2], a, bfi[2][kc]);
            MMA_TF32(acc[3], a, bfi[3][kc]);
        }
        #pragma unroll
        for (int kc = 0; kc < 8; ++kc) {
            int k = kc * 8 + lc;
            uint32_t a[4];
            a[0] = *(const uint32_t*)&Ahr[lr * ASTR + k];
            a[1] = *(const uint32_t*)&Ahr[(lr + 8) * ASTR + k];
            a[2] = *(const uint32_t*)&Ahr[lr * ASTR + k + 4];
            a[3] = *(const uint32_t*)&Ahr[(lr + 8) * ASTR + k + 4];
            MMA_TF32(acc[0], a, bfh[0][kc]);
            MMA_TF32(acc[1], a, bfh[1][kc]);
            MMA_TF32(acc[2], a, bfh[2][kc]);
            MMA_TF32(acc[3], a, bfh[3][kc]);
        }

        // ---- stage x(t+1) into the other buffer ----
        if (t + 1 < TT) {
            Axw[xrow * ASTR + xkk + 0] = tf32_rna(xnext.x);
            Axw[xrow * ASTR + xkk + 1] = tf32_rna(xnext.y);
            Axw[xrow * ASTR + xkk + 2] = tf32_rna(xnext.z);
            Axw[xrow * ASTR + xkk + 3] = tf32_rna(xnext.w);
        }

        // ---- epilogue: 2 rows x 2 units, thread-local ----
        #pragma unroll
        for (int rr = 0; rr < 2; ++rr) {
            int row = lr + 8 * rr;
            int j0  = rr * 2;
            float gi0 = sigf(acc[0][j0]);
            float gf0 = sigf(acc[1][j0]);
            float gg0 = tanhg(acc[2][j0]);
            float go0 = sigf(acc[3][j0]);
            float gi1 = sigf(acc[0][j0 + 1]);
            float gf1 = sigf(acc[1][j0 + 1]);
            float gg1 = tanhg(acc[2][j0 + 1]);
            float go1 = sigf(acc[3][j0 + 1]);

            float cn0 = gf0 * cst[j0]     + gi0 * gg0;
            float cn1 = gf1 * cst[j0 + 1] + gi1 * gg1;
            cst[j0]     = cn0;
            cst[j0 + 1] = cn1;
            float hn0 = go0 * tanhg(cn0);
            float hn1 = go1 * tanhg(cn1);

            *(float2*)&Ahw[row * ASTR + u0] =
                make_float2(tf32_rna(hn0), tf32_rna(hn1));

            if (write_all || t == TT - 1) {
                size_t trow = (size_t)t * BB + rowbase + row;
                *(float2*)&ouths[trow * HH + u0] = make_float2(hn0, hn1);
            }
        }
        __syncthreads();   // h(t+1) + x(t+1) visible for next step
    }
}

// ---------------------------------------------------------------------------
__global__ void fc_kernel(const float* __restrict__ hs,
                          const float* __restrict__ Wfc,
                          const float* __restrict__ bfc,
                          float* __restrict__ out) {
    int idx = blockIdx.x * blockDim.x + threadIdx.x;
    if (idx >= BB * OUTN) return;
    int b = idx / OUTN, o = idx - b * OUTN;
    const float* h = &hs[(size_t)(TT - 1) * (BB * HH) + (size_t)b * HH];
    float s = bfc[o];
    #pragma unroll
    for (int j = 0; j < HH; j++) s = fmaf(h[j], Wfc[o * HH + j], s);
    out[idx] = s;
}

// ---------------------------------------------------------------------------
extern "C" void kernel_launch(void* const* d_in, const int* in_sizes, int n_in,
                              void* d_out, int out_size) {
    const float* x     = (const float*)d_in[0];
    const float* W_ih0 = (const float*)d_in[1];
    const float* W_ihr = (const float*)d_in[2];
    const float* W_hh  = (const float*)d_in[3];
    const float* b_ih  = (const float*)d_in[4];
    const float* b_hh  = (const float*)d_in[5];
    const float* W_fc  = (const float*)d_in[6];
    const float* b_fc  = (const float*)d_in[7];
    float* out = (float*)d_out;

    float *hsA = nullptr, *hsB = nullptr, *xgp = nullptr, *biasp = nullptr;
    cudaGetSymbolAddress((void**)&hsA, g_hsA);
    cudaGetSymbolAddress((void**)&hsB, g_hsB);
    cudaGetSymbolAddress((void**)&xgp, g_xg);
    cudaGetSymbolAddress((void**)&biasp, g_bias);

    prep_kernel<<<LL * G4 / 256, 256>>>(b_ih, b_hh);

    // Layer 0: plane fill + plane-reading recurrence
    xg0_kernel<<<(int)(PLANE / 256), 256>>>(x, W_ih0, biasp, xgp);
    lstm_rec_mma<<<BB / 16, 256>>>(xgp, W_hh, hsA, 1);

    // Layers 1-3: fused recurrence (x.W_ih inside the step MMA chain)
    float* hs_in  = hsA;
    float* hs_out = hsB;
    for (int l = 1; l < LL; ++l) {
        lstm_rec_fused<<<BB / 16, 256>>>(
            hs_in,
            W_ihr + (size_t)(l - 1) * (G4 * HH),
            W_hh + (size_t)l * (G4 * HH),
            biasp + l * G4,
            hs_out, l < LL - 1 ? 1 : 0);
        float* tmp = hs_in; hs_in = hs_out; hs_out = tmp;
    }

    fc_kernel<<<(BB * OUTN + 255) / 256, 256>>>(hs_in, W_fc, b_fc, out);
}

// round 14
// speedup vs baseline: 4.3703x; 1.6288x over previous
#include <cuda_runtime.h>
#include <cuda_fp16.h>
#include <cstddef>
#include <cstdint>

// Problem constants
#define BB   2048
#define TT   512
#define D_IN 4
#define HH   64
#define LL   4
#define OUTN 5
#define G4   256   // 4*H

// -------------------------- device scratch --------------------------------
__device__ __half g_hsA[(size_t)TT * BB * HH];    // 128 MB ping (half)
__device__ __half g_hsB[(size_t)TT * BB * HH];    // 128 MB pong (half)
__device__ float  g_bias[LL][G4];

__device__ __forceinline__ float sigf(float x) {
    return __fdividef(1.0f, 1.0f + __expf(-x));
}
__device__ __forceinline__ float tanhg(float x) {
    return __fdividef(2.0f, 1.0f + __expf(-2.0f * x)) - 1.0f;
}

union H2U { __half2 h; uint32_t u; };
__device__ __forceinline__ uint32_t pack_h2(float a, float b) {
    H2U v; v.h = __floats2half2_rn(a, b); return v.u;
}

// fp16 MMA, f32 accumulate: A row-major 16x16, B col-major 16x8.
#define MMA_F16(c, a, b) \
    asm volatile("mma.sync.aligned.m16n8k16.row.col.f32.f16.f16.f32 " \
        "{%0,%1,%2,%3}, {%4,%5,%6,%7}, {%8,%9}, {%0,%1,%2,%3};" \
        : "+f"((c)[0]), "+f"((c)[1]), "+f"((c)[2]), "+f"((c)[3]) \
        : "r"((a)[0]), "r"((a)[1]), "r"((a)[2]), "r"((a)[3]), \
          "r"((b)[0]), "r"((b)[1]))

// SMEM A tiles: halfs, row stride 72 halfs (36 words; 36 mod 32 = 4 ->
// conflict-free frag loads: bank = 4*lr + lc + const).
#define ASTRH 72
#define AST2  36   // uint32 words per row

// ---------------------------------------------------------------------------
__global__ void prep_kernel(const float* __restrict__ b_ih,
                            const float* __restrict__ b_hh) {
    int idx = blockIdx.x * blockDim.x + threadIdx.x;
    if (idx >= LL * G4) return;
    g_bias[idx >> 8][idx & 255] = b_ih[idx] + b_hh[idx];
}

// ====================== fused fp16 recurrence (all layers) =================
// A = [x_t | h_t] as half tiles (double-buffered). W_ih/W_hh frags in regs.
// L0: x is the raw input [b][t][4], zero-padded to one K=16 chunk.
// Else: x = hs_prev (half, [t][b][u]), 4 K=16 chunks.
template <bool L0>
__global__ void __launch_bounds__(256, 1)
lstm_rec_f16(const float* __restrict__ xin, const __half* __restrict__ hs_prev,
             const float* __restrict__ Wih, const float* __restrict__ Whh,
             const float* __restrict__ bias, __half* __restrict__ ouths,
             int write_all) {
    __shared__ __half Ax[2][16 * ASTRH];
    __shared__ __half Ah[2][16 * ASTRH];

    const int tid  = threadIdx.x;
    const int wid  = tid >> 5;
    const int lane = tid & 31;
    const int lr   = lane >> 2;
    const int lc   = lane & 3;
    const int rowbase = blockIdx.x * 16;
    constexpr int XKC = L0 ? 1 : 4;

    // ---- weight fragments -> registers ----
    // b0 = {W[n][kb+2lc], W[n][kb+2lc+1]}, b1 = {W[n][kb+2lc+8], +9}
    uint32_t bfh[4][4][2];
    uint32_t bfi[4][XKC][2];
    {
        int n = (wid * 8 + lr);   // within gate block q: gate = q*64 + n
        #pragma unroll
        for (int q = 0; q < 4; ++q) {
            int g = q * 64 + n;
            #pragma unroll
            for (int kc = 0; kc < 4; ++kc) {
                int kb = kc * 16;
                bfh[q][kc][0] = pack_h2(Whh[g * HH + kb + 2 * lc],
                                        Whh[g * HH + kb + 2 * lc + 1]);
                bfh[q][kc][1] = pack_h2(Whh[g * HH + kb + 2 * lc + 8],
                                        Whh[g * HH + kb + 2 * lc + 9]);
            }
            if (L0) {
                // K=4 real, padded to 16: only k<4 nonzero.
                uint32_t b0 = 0;
                if (lc < 2)
                    b0 = pack_h2(Wih[g * D_IN + 2 * lc],
                                 Wih[g * D_IN + 2 * lc + 1]);
                bfi[q][0][0] = b0;
                bfi[q][0][1] = 0;
            } else {
                #pragma unroll
                for (int kc = 0; kc < 4; ++kc) {
                    int kb = kc * 16;
                    bfi[q][kc][0] = pack_h2(Wih[g * HH + kb + 2 * lc],
                                            Wih[g * HH + kb + 2 * lc + 1]);
                    bfi[q][kc][1] = pack_h2(Wih[g * HH + kb + 2 * lc + 8],
                                            Wih[g * HH + kb + 2 * lc + 9]);
                }
            }
        }
    }

    const int u0 = wid * 8 + 2 * lc;
    float2 bias_r[4];
    #pragma unroll
    for (int q = 0; q < 4; ++q)
        bias_r[q] = *(const float2*)&bias[q * 64 + u0];

    // ---- init: zero everything, stage x(0) ----
    for (int i = tid; i < 16 * ASTRH; i += 256) {
        Ah[0][i] = __float2half(0.f); Ah[1][i] = __float2half(0.f);
        Ax[0][i] = __float2half(0.f); Ax[1][i] = __float2half(0.f);
    }
    __syncthreads();
    if (L0) {
        if (tid < 16) {
            float4 v = *(const float4*)&xin[(size_t)(rowbase + tid) * (TT * D_IN)];
            uint32_t* ax = (uint32_t*)&Ax[0][0];
            ax[tid * AST2 + 0] = pack_h2(v.x, v.y);
            ax[tid * AST2 + 1] = pack_h2(v.z, v.w);
        }
    } else {
        const uint32_t* src = (const uint32_t*)hs_prev;
        uint32_t* ax = (uint32_t*)&Ax[0][0];
        #pragma unroll
        for (int p = 0; p < 2; ++p) {
            int idx = tid + p * 256;           // 0..511
            int row = idx >> 5, kp = idx & 31;
            ax[row * AST2 + kp] = src[((size_t)(rowbase + row)) * 32 + kp];
        }
    }
    __syncthreads();

    float cst[4] = {0.f, 0.f, 0.f, 0.f};
    uint32_t* outu = (uint32_t*)ouths;

    for (int t = 0; t < TT; ++t) {
        const __half* Axr = Ax[t & 1];
        const __half* Ahr = Ah[t & 1];
        __half*       Axw = Ax[(t + 1) & 1];
        __half*       Ahw = Ah[(t + 1) & 1];

        // ---- prefetch x(t+1) ----
        float4  xnext0;
        uint32_t xnext[2];
        if (t + 1 < TT) {
            if (L0) {
                if (tid < 16)
                    xnext0 = *(const float4*)&xin[((size_t)(rowbase + tid) * TT
                                                   + t + 1) * D_IN];
            } else {
                const uint32_t* src = (const uint32_t*)hs_prev;
                #pragma unroll
                for (int p = 0; p < 2; ++p) {
                    int idx = tid + p * 256;
                    int row = idx >> 5, kp = idx & 31;
                    xnext[p] = src[((size_t)(t + 1) * BB + rowbase + row) * 32 + kp];
                }
            }
        }

        // ---- MMA: acc[q] = bias + x.W_ih^T + h.W_hh^T ----
        float acc[4][4];
        #pragma unroll
        for (int q = 0; q < 4; ++q) {
            acc[q][0] = bias_r[q].x; acc[q][1] = bias_r[q].y;
            acc[q][2] = bias_r[q].x; acc[q][3] = bias_r[q].y;
        }

        #pragma unroll
        for (int kc = 0; kc < XKC; ++kc) {
            int k = kc * 16 + 2 * lc;   // even -> 4B-aligned half2
            uint32_t a[4];
            a[0] = *(const uint32_t*)&Axr[lr * ASTRH + k];
            a[1] = *(const uint32_t*)&Axr[(lr + 8) * ASTRH + k];
            a[2] = *(const uint32_t*)&Axr[lr * ASTRH + k + 8];
            a[3] = *(const uint32_t*)&Axr[(lr + 8) * ASTRH + k + 8];
            MMA_F16(acc[0], a, bfi[0][kc]);
            MMA_F16(acc[1], a, bfi[1][kc]);
            MMA_F16(acc[2], a, bfi[2][kc]);
            MMA_F16(acc[3], a, bfi[3][kc]);
        }
        #pragma unroll
        for (int kc = 0; kc < 4; ++kc) {
            int k = kc * 16 + 2 * lc;
            uint32_t a[4];
            a[0] = *(const uint32_t*)&Ahr[lr * ASTRH + k];
            a[1] = *(const uint32_t*)&Ahr[(lr + 8) * ASTRH + k];
            a[2] = *(const uint32_t*)&Ahr[lr * ASTRH + k + 8];
            a[3] = *(const uint32_t*)&Ahr[(lr + 8) * ASTRH + k + 8];
            MMA_F16(acc[0], a, bfh[0][kc]);
            MMA_F16(acc[1], a, bfh[1][kc]);
            MMA_F16(acc[2], a, bfh[2][kc]);
            MMA_F16(acc[3], a, bfh[3][kc]);
        }

        // ---- stage x(t+1) ----
        if (t + 1 < TT) {
            if (L0) {
                if (tid < 16) {
                    uint32_t* ax = (uint32_t*)Axw;
                    ax[tid * AST2 + 0] = pack_h2(xnext0.x, xnext0.y);
                    ax[tid * AST2 + 1] = pack_h2(xnext0.z, xnext0.w);
                }
            } else {
                uint32_t* ax = (uint32_t*)Axw;
                #pragma unroll
                for (int p = 0; p < 2; ++p) {
                    int idx = tid + p * 256;
                    int row = idx >> 5, kp = idx & 31;
                    ax[row * AST2 + kp] = xnext[p];
                }
            }
        }

        // ---- epilogue: 2 rows x 2 units, thread-local ----
        #pragma unroll
        for (int rr = 0; rr < 2; ++rr) {
            int row = lr + 8 * rr;
            int j0  = rr * 2;
            float gi0 = sigf(acc[0][j0]);
            float gf0 = sigf(acc[1][j0]);
            float gg0 = tanhg(acc[2][j0]);
            float go0 = sigf(acc[3][j0]);
            float gi1 = sigf(acc[0][j0 + 1]);
            float gf1 = sigf(acc[1][j0 + 1]);
            float gg1 = tanhg(acc[2][j0 + 1]);
            float go1 = sigf(acc[3][j0 + 1]);

            float cn0 = gf0 * cst[j0]     + gi0 * gg0;
            float cn1 = gf1 * cst[j0 + 1] + gi1 * gg1;
            cst[j0]     = cn0;
            cst[j0 + 1] = cn1;
            float hn0 = go0 * tanhg(cn0);
            float hn1 = go1 * tanhg(cn1);

            uint32_t hpk = pack_h2(hn0, hn1);
            *(uint32_t*)&Ahw[row * ASTRH + u0] = hpk;

            if (write_all || t == TT - 1) {
                size_t trow = (size_t)t * BB + rowbase + row;
                outu[trow * 32 + 4 * wid + lc] = hpk;
            }
        }
        __syncthreads();   // x(t+1)/h(t+1) visible for next step
    }
}

// ---------------------------------------------------------------------------
__global__ void fc_kernel(const __half* __restrict__ hs,
                          const float* __restrict__ Wfc,
                          const float* __restrict__ bfc,
                          float* __restrict__ out) {
    int idx = blockIdx.x * blockDim.x + threadIdx.x;
    if (idx >= BB * OUTN) return;
    int b = idx / OUTN, o = idx - b * OUTN;
    const __half* h = &hs[(size_t)(TT - 1) * (BB * HH) + (size_t)b * HH];
    float s = bfc[o];
    #pragma unroll
    for (int j = 0; j < HH; j++)
        s = fmaf(__half2float(h[j]), Wfc[o * HH + j], s);
    out[idx] = s;
}

// ---------------------------------------------------------------------------
extern "C" void kernel_launch(void* const* d_in, const int* in_sizes, int n_in,
                              void* d_out, int out_size) {
    const float* x     = (const float*)d_in[0];
    const float* W_ih0 = (const float*)d_in[1];
    const float* W_ihr = (const float*)d_in[2];
    const float* W_hh  = (const float*)d_in[3];
    const float* b_ih  = (const float*)d_in[4];
    const float* b_hh  = (const float*)d_in[5];
    const float* W_fc  = (const float*)d_in[6];
    const float* b_fc  = (const float*)d_in[7];
    float* out = (float*)d_out;

    __half *hsA = nullptr, *hsB = nullptr;
    float* biasp = nullptr;
    cudaGetSymbolAddress((void**)&hsA, g_hsA);
    cudaGetSymbolAddress((void**)&hsB, g_hsB);
    cudaGetSymbolAddress((void**)&biasp, g_bias);

    prep_kernel<<<LL * G4 / 256, 256>>>(b_ih, b_hh);

    // Layer 0 (fused, padded K=16 input chunk)
    lstm_rec_f16<true><<<BB / 16, 256>>>(
        x, nullptr, W_ih0, W_hh, biasp, hsA, 1);

    // Layers 1-3 (fused)
    __half* hs_in  = hsA;
    __half* hs_out = hsB;
    for (int l = 1; l < LL; ++l) {
        lstm_rec_f16<false><<<BB / 16, 256>>>(
            nullptr, hs_in,
            W_ihr + (size_t)(l - 1) * (G4 * HH),
            W_hh + (size_t)l * (G4 * HH),
            biasp + l * G4,
            hs_out, l < LL - 1 ? 1 : 0);
        __half* tmp = hs_in; hs_in = hs_out; hs_out = tmp;
    }

    fc_kernel<<<(BB * OUTN + 255) / 256, 256>>>(hs_in, W_fc, b_fc, out);
}